// round 4
// baseline (speedup 1.0000x reference)
#include <cuda_runtime.h>

#define SEQ 4096
#define EMB 1024
#define NH 16
#define HD 64

// Scratch for the QKV projection output: [4096, 3072] fp32 (48 MB).
// __device__ global = allowed scratch (no runtime allocation).
__device__ float g_qkv[SEQ * 3 * EMB];

// ---------------------------------------------------------------------------
// Kernel 1: QKV GEMM.  C[m,n] = sum_k A[m,k] * W[n,k] + bias[n]
//   A = hidden [4096,1024] row-major, W = [3072,1024] row-major (NT GEMM).
//   Tiles: BM=128, BN=128, BK=16, 256 threads, 8x8 per thread.
// ---------------------------------------------------------------------------
__global__ __launch_bounds__(256, 2)
void qkv_gemm_kernel(const float* __restrict__ A,
                     const float* __restrict__ W,
                     const float* __restrict__ bias)
{
    __shared__ float As[16 * 132];   // [k][m], pad 132 keeps float4 alignment
    __shared__ float Ws[16 * 132];   // [k][n]

    const int bm = blockIdx.y * 128;
    const int bn = blockIdx.x * 128;
    const int t  = threadIdx.x;
    const int tx = t & 15;           // n-tile coord (8 cols each)
    const int ty = t >> 4;           // m-tile coord (8 rows each)

    float acc[8][8];
    #pragma unroll
    for (int i = 0; i < 8; ++i)
        #pragma unroll
        for (int j = 0; j < 8; ++j) acc[i][j] = 0.f;

    for (int kk = 0; kk < EMB; kk += 16) {
        // Load A and W tiles (each 128x16 floats = 512 float4, 2 per thread),
        // storing k-major into shared.
        #pragma unroll
        for (int it = 0; it < 2; ++it) {
            int f  = t + it * 256;      // 0..511
            int r  = f >> 2;            // 0..127
            int kq = (f & 3) << 2;      // 0,4,8,12
            float4 av = *(const float4*)&A[(bm + r) * EMB + kk + kq];
            As[(kq + 0) * 132 + r] = av.x;
            As[(kq + 1) * 132 + r] = av.y;
            As[(kq + 2) * 132 + r] = av.z;
            As[(kq + 3) * 132 + r] = av.w;
            float4 wv = *(const float4*)&W[(bn + r) * EMB + kk + kq];
            Ws[(kq + 0) * 132 + r] = wv.x;
            Ws[(kq + 1) * 132 + r] = wv.y;
            Ws[(kq + 2) * 132 + r] = wv.z;
            Ws[(kq + 3) * 132 + r] = wv.w;
        }
        __syncthreads();

        #pragma unroll
        for (int k = 0; k < 16; ++k) {
            float4 a0 = *(const float4*)&As[k * 132 + ty * 8];
            float4 a1 = *(const float4*)&As[k * 132 + ty * 8 + 4];
            float4 b0 = *(const float4*)&Ws[k * 132 + tx * 8];
            float4 b1 = *(const float4*)&Ws[k * 132 + tx * 8 + 4];
            float a[8] = {a0.x, a0.y, a0.z, a0.w, a1.x, a1.y, a1.z, a1.w};
            float b[8] = {b0.x, b0.y, b0.z, b0.w, b1.x, b1.y, b1.z, b1.w};
            #pragma unroll
            for (int i = 0; i < 8; ++i)
                #pragma unroll
                for (int j = 0; j < 8; ++j)
                    acc[i][j] += a[i] * b[j];
        }
        __syncthreads();
    }

    // Epilogue: add bias, store to g_qkv.
    const int nbase = bn + tx * 8;
    float bj[8];
    #pragma unroll
    for (int j = 0; j < 8; ++j) bj[j] = bias[nbase + j];

    #pragma unroll
    for (int i = 0; i < 8; ++i) {
        int m = bm + ty * 8 + i;
        float4 r0 = make_float4(acc[i][0] + bj[0], acc[i][1] + bj[1],
                                acc[i][2] + bj[2], acc[i][3] + bj[3]);
        float4 r1 = make_float4(acc[i][4] + bj[4], acc[i][5] + bj[5],
                                acc[i][6] + bj[6], acc[i][7] + bj[7]);
        *(float4*)&g_qkv[m * (3 * EMB) + nbase]     = r0;
        *(float4*)&g_qkv[m * (3 * EMB) + nbase + 4] = r1;
    }
}

// ---------------------------------------------------------------------------
// Kernel 2: flash attention (fp32) + fused Hebbian diagonal scale.
//   Per block: one head, one 128-row Q tile. KV streamed in 64-row tiles.
//   Thread map: 16x16 grid; each thread owns 8 rows x 4 cols.
//   Row-softmax reductions are half-warp shfl_xor (row group = 16 lanes).
// ---------------------------------------------------------------------------
#define BQ 128
#define BK 64
#define DP 68     // padded row length (floats): keeps float4 alignment,
                  // conflict-free LDS.128 for tx-strided column loads

#define SM_Q 0
#define SM_K (BQ * DP)
#define SM_V (SM_K + BK * DP)
#define SM_P (SM_V + BK * DP)
#define SM_FLOATS (SM_P + BQ * DP)
#define SMEM_BYTES (SM_FLOATS * 4)   // 104448 bytes

__global__ __launch_bounds__(256, 2)
void attn_kernel(const float* __restrict__ trace,   // [16,64,64]
                 float* __restrict__ out)           // [4096,1024]
{
    extern __shared__ float sm[];
    float* Qs = sm + SM_Q;
    float* Ks = sm + SM_K;
    float* Vs = sm + SM_V;
    float* Ps = sm + SM_P;

    const int h  = blockIdx.y;
    const int q0 = blockIdx.x * BQ;
    const int t  = threadIdx.x;
    const int tx = t & 15;    // 4 d/score cols each
    const int ty = t >> 4;    // 8 rows each

    const float* qkv = g_qkv;

    // Load Q tile, pre-scaled by 1/sqrt(D) = 0.125.
    #pragma unroll
    for (int w = 0; w < 8; ++w) {
        int f  = t + w * 256;        // float4 index, 0..2047
        int r  = f >> 4;             // 0..127
        int c4 = (f & 15) << 2;      // 0..60
        float4 v = *(const float4*)&qkv[(q0 + r) * (3 * EMB) + h * HD + c4];
        Qs[r * DP + c4 + 0] = v.x * 0.125f;
        Qs[r * DP + c4 + 1] = v.y * 0.125f;
        Qs[r * DP + c4 + 2] = v.z * 0.125f;
        Qs[r * DP + c4 + 3] = v.w * 0.125f;
    }

    float m_i[8], l_i[8], o[8][4];
    #pragma unroll
    for (int i = 0; i < 8; ++i) {
        m_i[i] = -1e30f;
        l_i[i] = 0.f;
        #pragma unroll
        for (int j = 0; j < 4; ++j) o[i][j] = 0.f;
    }

    for (int kv0 = 0; kv0 < SEQ; kv0 += BK) {
        __syncthreads();   // previous iteration's P/V reads done

        // Load K and V tiles (64x64 each; 4 float4 per thread per tile).
        #pragma unroll
        for (int w = 0; w < 4; ++w) {
            int f  = t + w * 256;      // 0..1023
            int r  = f >> 4;           // 0..63
            int c4 = (f & 15) << 2;
            float4 kv = *(const float4*)&qkv[(kv0 + r) * (3 * EMB) + EMB + h * HD + c4];
            Ks[r * DP + c4 + 0] = kv.x;
            Ks[r * DP + c4 + 1] = kv.y;
            Ks[r * DP + c4 + 2] = kv.z;
            Ks[r * DP + c4 + 3] = kv.w;
            float4 vv = *(const float4*)&qkv[(kv0 + r) * (3 * EMB) + 2 * EMB + h * HD + c4];
            Vs[r * DP + c4 + 0] = vv.x;
            Vs[r * DP + c4 + 1] = vv.y;
            Vs[r * DP + c4 + 2] = vv.z;
            Vs[r * DP + c4 + 3] = vv.w;
        }
        __syncthreads();

        // S = Qs @ Ks^T   (8x4 per thread)
        float s[8][4];
        #pragma unroll
        for (int i = 0; i < 8; ++i)
            #pragma unroll
            for (int j = 0; j < 4; ++j) s[i][j] = 0.f;

        #pragma unroll 4
        for (int d4 = 0; d4 < 16; ++d4) {
            float4 k4[4];
            #pragma unroll
            for (int j = 0; j < 4; ++j)
                k4[j] = *(const float4*)&Ks[(tx * 4 + j) * DP + d4 * 4];
            #pragma unroll
            for (int i = 0; i < 8; ++i) {
                float4 q4 = *(const float4*)&Qs[(ty * 8 + i) * DP + d4 * 4];
                #pragma unroll
                for (int j = 0; j < 4; ++j) {
                    s[i][j] += q4.x * k4[j].x;
                    s[i][j] += q4.y * k4[j].y;
                    s[i][j] += q4.z * k4[j].z;
                    s[i][j] += q4.w * k4[j].w;
                }
            }
        }

        // Online softmax update; write P (=exp(s-m)) to shared.
        #pragma unroll
        for (int i = 0; i < 8; ++i) {
            float rm = fmaxf(fmaxf(s[i][0], s[i][1]), fmaxf(s[i][2], s[i][3]));
            #pragma unroll
            for (int w = 1; w < 16; w <<= 1)
                rm = fmaxf(rm, __shfl_xor_sync(0xffffffffu, rm, w));
            float mnew  = fmaxf(m_i[i], rm);
            float alpha = __expf(m_i[i] - mnew);
            m_i[i] = mnew;
            float rs = 0.f;
            #pragma unroll
            for (int j = 0; j < 4; ++j) {
                s[i][j] = __expf(s[i][j] - mnew);
                rs += s[i][j];
            }
            #pragma unroll
            for (int w = 1; w < 16; w <<= 1)
                rs += __shfl_xor_sync(0xffffffffu, rs, w);
            l_i[i] = l_i[i] * alpha + rs;
            #pragma unroll
            for (int j = 0; j < 4; ++j) o[i][j] *= alpha;
            *(float4*)&Ps[(ty * 8 + i) * DP + tx * 4] =
                make_float4(s[i][0], s[i][1], s[i][2], s[i][3]);
        }
        __syncthreads();

        // O += P @ V
        #pragma unroll 8
        for (int c = 0; c < BK; ++c) {
            float4 v4 = *(const float4*)&Vs[c * DP + tx * 4];
            #pragma unroll
            for (int i = 0; i < 8; ++i) {
                float p = Ps[(ty * 8 + i) * DP + c];
                o[i][0] += p * v4.x;
                o[i][1] += p * v4.y;
                o[i][2] += p * v4.z;
                o[i][3] += p * v4.w;
            }
        }
    }

    // Epilogue: 1/l normalize, Hebbian diagonal scale, store.
    float dd[4];
    #pragma unroll
    for (int j = 0; j < 4; ++j) {
        int d = tx * 4 + j;
        dd[j] = trace[h * HD * HD + d * HD + d];   // trace[h][d][d]
    }
    #pragma unroll
    for (int i = 0; i < 8; ++i) {
        float inv = 1.f / l_i[i];
        float4 res = make_float4(o[i][0] * inv * dd[0],
                                 o[i][1] * inv * dd[1],
                                 o[i][2] * inv * dd[2],
                                 o[i][3] * inv * dd[3]);
        *(float4*)&out[(q0 + ty * 8 + i) * EMB + h * HD + tx * 4] = res;
    }
}

// ---------------------------------------------------------------------------
extern "C" void kernel_launch(void* const* d_in, const int* in_sizes, int n_in,
                              void* d_out, int out_size)
{
    (void)in_sizes; (void)n_in; (void)out_size;
    const float* hidden = (const float*)d_in[0];   // [1,4096,1024]
    const float* W      = (const float*)d_in[1];   // [3072,1024]
    const float* bias   = (const float*)d_in[2];   // [3072]
    const float* trace  = (const float*)d_in[3];   // [16,64,64]
    float* out = (float*)d_out;                    // [1,4096,1024]

    qkv_gemm_kernel<<<dim3(3 * EMB / 128, SEQ / 128), 256>>>(hidden, W, bias);

    cudaFuncSetAttribute(attn_kernel,
                         cudaFuncAttributeMaxDynamicSharedMemorySize,
                         SMEM_BYTES);
    attn_kernel<<<dim3(SEQ / BQ, NH), 256, SMEM_BYTES>>>(trace, out);
}

// round 9
// speedup vs baseline: 2.7268x; 2.7268x over previous
#include <cuda_runtime.h>
#include <cuda_bf16.h>
#include <stdint.h>

#define SEQ 4096
#define EMB 1024
#define NH 16
#define HD 64
#define QKV_COLS 3072
#define QKV_C2 1536          // uint2 columns of the split qkv

// ---- static device scratch (no runtime allocation) ----
__device__ __align__(16) uint2 g_A_split[SEQ * (EMB / 2)];        // [4096][512]
__device__ __align__(16) uint2 g_W_split[QKV_COLS * (EMB / 2)];   // [3072][512]
__device__ __align__(16) uint2 g_qkv_split[SEQ * QKV_C2];         // [4096][1536]
__device__ __align__(16) uint2 g_vT_split[NH * HD * (SEQ / 2)];   // [16][64][2048]

// ---------------------------------------------------------------------------
// helpers
// ---------------------------------------------------------------------------
// Split (x0,x1) fp32 -> {bf16-pair hi, bf16-pair lo}. low halfword = x0.
__device__ __forceinline__ uint2 split2(float x0, float x1) {
    uint32_t hp, lp;
    asm("cvt.rn.bf16x2.f32 %0, %1, %2;" : "=r"(hp) : "f"(x1), "f"(x0));
    __nv_bfloat162 hb = *reinterpret_cast<__nv_bfloat162*>(&hp);
    float2 back = __bfloat1622float2(hb);
    float r0 = x0 - back.x;
    float r1 = x1 - back.y;
    asm("cvt.rn.bf16x2.f32 %0, %1, %2;" : "=r"(lp) : "f"(r1), "f"(r0));
    return make_uint2(hp, lp);
}

// D(16x8,f32) += A(16x16,bf16) * B(16x8,bf16)
__device__ __forceinline__ void mma16816(float* d, const uint32_t* a,
                                         uint32_t b0, uint32_t b1) {
    asm volatile(
        "mma.sync.aligned.m16n8k16.row.col.f32.bf16.bf16.f32 "
        "{%0,%1,%2,%3}, {%4,%5,%6,%7}, {%8,%9}, {%0,%1,%2,%3};"
        : "+f"(d[0]), "+f"(d[1]), "+f"(d[2]), "+f"(d[3])
        : "r"(a[0]), "r"(a[1]), "r"(a[2]), "r"(a[3]), "r"(b0), "r"(b1));
}

// ---------------------------------------------------------------------------
// Prep: fp32 -> split-bf16 pairs
// ---------------------------------------------------------------------------
__global__ void split_kernel(const float4* __restrict__ src,
                             uint2* __restrict__ dst, int n4) {
    int i = blockIdx.x * blockDim.x + threadIdx.x;
    if (i >= n4) return;
    float4 v = src[i];
    dst[2 * i]     = split2(v.x, v.y);
    dst[2 * i + 1] = split2(v.z, v.w);
}

// ---------------------------------------------------------------------------
// Kernel 1: QKV GEMM, bf16x3 mma.  C[4096,3072] = A @ W^T + bias
//   128x128x32 tile, 256 threads; warp grid 4(M)x2(N), warp tile 32x64.
//   Q columns (n < 1024) pre-scaled by 1/sqrt(64)=0.125.
// ---------------------------------------------------------------------------
#define G_AS 20   // smem row stride in uint2 (160B = 40 banks ≡ 8 mod 32)

__global__ __launch_bounds__(256)
void qkv_gemm_mma(const float* __restrict__ bias) {
    extern __shared__ uint2 smg[];
    uint2* As = smg;                       // [2][128*G_AS]
    uint2* Bs = smg + 2 * 128 * G_AS;      // [2][128*G_AS]
    uint4* As4 = reinterpret_cast<uint4*>(As);
    uint4* Bs4 = reinterpret_cast<uint4*>(Bs);

    const int t = threadIdx.x;
    const int warp = t >> 5, lane = t & 31;
    const int g = lane >> 2, tq = lane & 3;
    const int wm = warp & 3;      // row warp
    const int wn = warp >> 2;     // col warp
    const int bm = blockIdx.y * 128;
    const int bn = blockIdx.x * 128;

    const uint4* A4 = reinterpret_cast<const uint4*>(g_A_split);
    const uint4* B4 = reinterpret_cast<const uint4*>(g_W_split);

    const int lr = t >> 3;       // loader row 0..31 (+32*i)
    const int lc = t & 7;        // loader uint4 col 0..7

    float acc[2][8][4];
    #pragma unroll
    for (int mt = 0; mt < 2; ++mt)
        #pragma unroll
        for (int nt = 0; nt < 8; ++nt)
            #pragma unroll
            for (int j = 0; j < 4; ++j) acc[mt][nt][j] = 0.f;

    uint4 pa[4], pb[4];
    // preload kt = 0
    #pragma unroll
    for (int i = 0; i < 4; ++i) {
        int r = lr + i * 32;
        pa[i] = A4[(bm + r) * 256 + lc];
        pb[i] = B4[(bn + r) * 256 + lc];
    }
    #pragma unroll
    for (int i = 0; i < 4; ++i) {
        int r = lr + i * 32;
        As4[r * 10 + lc] = pa[i];
        Bs4[r * 10 + lc] = pb[i];
    }
    __syncthreads();

    for (int kt = 0; kt < 32; ++kt) {
        const int cur = kt & 1;
        if (kt < 31) {
            #pragma unroll
            for (int i = 0; i < 4; ++i) {
                int r = lr + i * 32;
                pa[i] = A4[(bm + r) * 256 + (kt + 1) * 8 + lc];
                pb[i] = B4[(bn + r) * 256 + (kt + 1) * 8 + lc];
            }
        }
        const uint2* Ab = As + cur * (128 * G_AS);
        const uint2* Bb = Bs + cur * (128 * G_AS);

        #pragma unroll
        for (int ks = 0; ks < 2; ++ks) {
            const int k2b = ks * 8;
            uint32_t ah[2][4], al[2][4];
            #pragma unroll
            for (int mt = 0; mt < 2; ++mt) {
                int row = wm * 32 + mt * 16 + g;
                uint2 f0 = Ab[row * G_AS + k2b + tq];
                uint2 f1 = Ab[(row + 8) * G_AS + k2b + tq];
                uint2 f2 = Ab[row * G_AS + k2b + tq + 4];
                uint2 f3 = Ab[(row + 8) * G_AS + k2b + tq + 4];
                ah[mt][0] = f0.x; al[mt][0] = f0.y;
                ah[mt][1] = f1.x; al[mt][1] = f1.y;
                ah[mt][2] = f2.x; al[mt][2] = f2.y;
                ah[mt][3] = f3.x; al[mt][3] = f3.y;
            }
            uint32_t bh[8][2], bl[8][2];
            #pragma unroll
            for (int nt = 0; nt < 8; ++nt) {
                int col = wn * 64 + nt * 8 + g;
                uint2 e0 = Bb[col * G_AS + k2b + tq];
                uint2 e1 = Bb[col * G_AS + k2b + tq + 4];
                bh[nt][0] = e0.x; bl[nt][0] = e0.y;
                bh[nt][1] = e1.x; bl[nt][1] = e1.y;
            }
            #pragma unroll
            for (int mt = 0; mt < 2; ++mt)
                #pragma unroll
                for (int nt = 0; nt < 8; ++nt) {
                    mma16816(acc[mt][nt], ah[mt], bh[nt][0], bh[nt][1]);
                    mma16816(acc[mt][nt], al[mt], bh[nt][0], bh[nt][1]);
                    mma16816(acc[mt][nt], ah[mt], bl[nt][0], bl[nt][1]);
                }
        }
        if (kt < 31) {
            uint4* Ad = As4 + (cur ^ 1) * (128 * G_AS / 2);
            uint4* Bd = Bs4 + (cur ^ 1) * (128 * G_AS / 2);
            #pragma unroll
            for (int i = 0; i < 4; ++i) {
                int r = lr + i * 32;
                Ad[r * 10 + lc] = pa[i];
                Bd[r * 10 + lc] = pb[i];
            }
        }
        __syncthreads();
    }

    // epilogue: + bias, Q scale, split to bf16 pairs, store
    const float scale = (bn < EMB) ? 0.125f : 1.0f;
    #pragma unroll
    for (int mt = 0; mt < 2; ++mt) {
        int r0 = bm + wm * 32 + mt * 16 + g;
        #pragma unroll
        for (int nt = 0; nt < 8; ++nt) {
            int col0 = bn + wn * 64 + nt * 8 + 2 * tq;
            float b0 = bias[col0], b1 = bias[col0 + 1];
            float v00 = (acc[mt][nt][0] + b0) * scale;
            float v01 = (acc[mt][nt][1] + b1) * scale;
            float v10 = (acc[mt][nt][2] + b0) * scale;
            float v11 = (acc[mt][nt][3] + b1) * scale;
            g_qkv_split[r0 * QKV_C2 + (col0 >> 1)]       = split2(v00, v01);
            g_qkv_split[(r0 + 8) * QKV_C2 + (col0 >> 1)] = split2(v10, v11);
        }
    }
}

// ---------------------------------------------------------------------------
// Kernel 2: V transpose  qkv_split V region -> vT_split[h][d][m-pair]
//   V region starts at element 2*EMB = 2048 -> uint2 column 1024.
// ---------------------------------------------------------------------------
__global__ void vT_kernel() {
    int i = blockIdx.x * 256 + threadIdx.x;       // 16*64*2048 total
    int m2 = i & 2047;
    int d  = (i >> 11) & 63;
    int h  = i >> 17;
    int col = 1024 + h * 32 + (d >> 1);           // FIXED: V region = [1024,1536)
    uint2 p0 = g_qkv_split[(2 * m2) * QKV_C2 + col];
    uint2 p1 = g_qkv_split[(2 * m2 + 1) * QKV_C2 + col];
    uint32_t sh = (d & 1) ? 16 : 0;
    uint32_t h0 = (p0.x >> sh) & 0xffffu;
    uint32_t h1 = (p1.x >> sh) & 0xffffu;
    uint32_t l0 = (p0.y >> sh) & 0xffffu;
    uint32_t l1 = (p1.y >> sh) & 0xffffu;
    g_vT_split[((h * 64 + d) << 11) + m2] = make_uint2(h0 | (h1 << 16), l0 | (l1 << 16));
}

// ---------------------------------------------------------------------------
// Kernel 3: flash attention, bf16x3 mma + fused Hebbian diagonal.
//   Block = (q-tile 128, head). 8 warps x 16 q-rows. KV tiles of 64.
// ---------------------------------------------------------------------------
#define ABK 64
#define KV_S 36    // smem row stride in uint2 (288B = 72 banks ≡ 8 mod 32)

__global__ __launch_bounds__(256)
void attn_mma(const float* __restrict__ trace, float* __restrict__ out) {
    extern __shared__ uint2 sma[];
    uint2* Qs = sma;                           // [128][KV_S]
    uint2* Ks = sma + 128 * KV_S;              // [2][64][KV_S]
    uint2* Vs = Ks + 2 * 64 * KV_S;            // [2][64][KV_S]
    uint4* Qs4 = reinterpret_cast<uint4*>(Qs);
    uint4* Ks4 = reinterpret_cast<uint4*>(Ks);
    uint4* Vs4 = reinterpret_cast<uint4*>(Vs);

    const int t = threadIdx.x;
    const int warp = t >> 5, lane = t & 31;
    const int g = lane >> 2, tq = lane & 3;
    const int h = blockIdx.y;
    const int q0 = blockIdx.x * 128;

    const uint4* G4  = reinterpret_cast<const uint4*>(g_qkv_split);   // row = 768 uint4
    const uint4* VT4 = reinterpret_cast<const uint4*>(g_vT_split);    // row = 1024 uint4

    const int lr = t >> 4;    // 0..15
    const int lc = t & 15;    // uint4 col 0..15

    // ---- load Q tile to smem ----
    #pragma unroll
    for (int i = 0; i < 8; ++i) {
        int r = lr + i * 16;
        Qs4[r * 18 + lc] = G4[(q0 + r) * 768 + h * 16 + lc];
    }
    __syncthreads();

    // ---- Q fragments -> registers ----
    const int qr = warp * 16;
    uint32_t qh[4][4], ql[4][4];
    #pragma unroll
    for (int ks = 0; ks < 4; ++ks) {
        uint2 f0 = Qs[(qr + g) * KV_S + 8 * ks + tq];
        uint2 f1 = Qs[(qr + g + 8) * KV_S + 8 * ks + tq];
        uint2 f2 = Qs[(qr + g) * KV_S + 8 * ks + tq + 4];
        uint2 f3 = Qs[(qr + g + 8) * KV_S + 8 * ks + tq + 4];
        qh[ks][0] = f0.x; ql[ks][0] = f0.y;
        qh[ks][1] = f1.x; ql[ks][1] = f1.y;
        qh[ks][2] = f2.x; ql[ks][2] = f2.y;
        qh[ks][3] = f3.x; ql[ks][3] = f3.y;
    }

    // ---- preload KV tile 0 ----
    uint4 pk[4], pv[4];
    #pragma unroll
    for (int i = 0; i < 4; ++i) {
        int r = lr + i * 16;
        pk[i] = G4[r * 768 + 256 + h * 16 + lc];
        pv[i] = VT4[(h * 64 + r) * 1024 + lc];
    }
    #pragma unroll
    for (int i = 0; i < 4; ++i) {
        int r = lr + i * 16;
        Ks4[r * 18 + lc] = pk[i];
        Vs4[r * 18 + lc] = pv[i];
    }
    __syncthreads();

    float m0 = -1e30f, m1 = -1e30f, l0 = 0.f, l1 = 0.f;
    float o[8][4];
    #pragma unroll
    for (int nt = 0; nt < 8; ++nt)
        #pragma unroll
        for (int j = 0; j < 4; ++j) o[nt][j] = 0.f;

    for (int it = 0; it < SEQ / ABK; ++it) {
        const int cur = it & 1;
        if (it < SEQ / ABK - 1) {
            int kv0 = (it + 1) * ABK;
            #pragma unroll
            for (int i = 0; i < 4; ++i) {
                int r = lr + i * 16;
                pk[i] = G4[(kv0 + r) * 768 + 256 + h * 16 + lc];
                pv[i] = VT4[(h * 64 + r) * 1024 + (it + 1) * 16 + lc];
            }
        }
        const uint2* Kb = Ks + cur * (64 * KV_S);
        const uint2* Vb = Vs + cur * (64 * KV_S);

        // ---- S = Q @ K^T ----
        float s[8][4];
        #pragma unroll
        for (int nt = 0; nt < 8; ++nt)
            #pragma unroll
            for (int j = 0; j < 4; ++j) s[nt][j] = 0.f;

        #pragma unroll
        for (int ks = 0; ks < 4; ++ks) {
            #pragma unroll
            for (int nt = 0; nt < 8; ++nt) {
                int n = nt * 8 + g;
                uint2 e0 = Kb[n * KV_S + 8 * ks + tq];
                uint2 e1 = Kb[n * KV_S + 8 * ks + tq + 4];
                mma16816(s[nt], qh[ks], e0.x, e1.x);
                mma16816(s[nt], ql[ks], e0.x, e1.x);
                mma16816(s[nt], qh[ks], e0.y, e1.y);
            }
        }

        // ---- online softmax (quad reduction; rows g and g+8) ----
        float rm0 = -1e30f, rm1 = -1e30f;
        #pragma unroll
        for (int nt = 0; nt < 8; ++nt) {
            rm0 = fmaxf(rm0, fmaxf(s[nt][0], s[nt][1]));
            rm1 = fmaxf(rm1, fmaxf(s[nt][2], s[nt][3]));
        }
        #pragma unroll
        for (int w = 1; w < 4; w <<= 1) {
            rm0 = fmaxf(rm0, __shfl_xor_sync(0xffffffffu, rm0, w));
            rm1 = fmaxf(rm1, __shfl_xor_sync(0xffffffffu, rm1, w));
        }
        float n0 = fmaxf(m0, rm0), n1 = fmaxf(m1, rm1);
        float a0 = __expf(m0 - n0), a1 = __expf(m1 - n1);
        m0 = n0; m1 = n1;
        float rs0 = 0.f, rs1 = 0.f;
        #pragma unroll
        for (int nt = 0; nt < 8; ++nt) {
            s[nt][0] = __expf(s[nt][0] - n0);
            s[nt][1] = __expf(s[nt][1] - n0);
            s[nt][2] = __expf(s[nt][2] - n1);
            s[nt][3] = __expf(s[nt][3] - n1);
            rs0 += s[nt][0] + s[nt][1];
            rs1 += s[nt][2] + s[nt][3];
        }
        #pragma unroll
        for (int w = 1; w < 4; w <<= 1) {
            rs0 += __shfl_xor_sync(0xffffffffu, rs0, w);
            rs1 += __shfl_xor_sync(0xffffffffu, rs1, w);
        }
        l0 = l0 * a0 + rs0;
        l1 = l1 * a1 + rs1;
        #pragma unroll
        for (int nt = 0; nt < 8; ++nt) {
            o[nt][0] *= a0; o[nt][1] *= a0;
            o[nt][2] *= a1; o[nt][3] *= a1;
        }

        // ---- O += P @ V  (P stays in registers; c-layout == a-layout) ----
        #pragma unroll
        for (int ks = 0; ks < 4; ++ks) {
            uint32_t ph[4], pl[4];
            uint2 u;
            u = split2(s[2 * ks][0], s[2 * ks][1]);     ph[0] = u.x; pl[0] = u.y;
            u = split2(s[2 * ks][2], s[2 * ks][3]);     ph[1] = u.x; pl[1] = u.y;
            u = split2(s[2 * ks + 1][0], s[2 * ks + 1][1]); ph[2] = u.x; pl[2] = u.y;
            u = split2(s[2 * ks + 1][2], s[2 * ks + 1][3]); ph[3] = u.x; pl[3] = u.y;
            #pragma unroll
            for (int nt = 0; nt < 8; ++nt) {
                int n = nt * 8 + g;   // d index
                uint2 e0 = Vb[n * KV_S + 8 * ks + tq];
                uint2 e1 = Vb[n * KV_S + 8 * ks + tq + 4];
                mma16816(o[nt], ph, e0.x, e1.x);
                mma16816(o[nt], pl, e0.x, e1.x);
                mma16816(o[nt], ph, e0.y, e1.y);
            }
        }

        if (it < SEQ / ABK - 1) {
            uint4* Kd = Ks4 + (cur ^ 1) * (64 * KV_S / 2);
            uint4* Vd = Vs4 + (cur ^ 1) * (64 * KV_S / 2);
            #pragma unroll
            for (int i = 0; i < 4; ++i) {
                int r = lr + i * 16;
                Kd[r * 18 + lc] = pk[i];
                Vd[r * 18 + lc] = pv[i];
            }
        }
        __syncthreads();
    }

    // ---- epilogue: 1/l, Hebbian diag, store ----
    float inv0 = 1.f / l0, inv1 = 1.f / l1;
    int row0 = q0 + qr + g, row1 = row0 + 8;
    #pragma unroll
    for (int nt = 0; nt < 8; ++nt) {
        int d0 = nt * 8 + 2 * tq;
        float dd0 = trace[h * 4096 + d0 * 65];
        float dd1 = trace[h * 4096 + (d0 + 1) * 65];
        float2 r0 = make_float2(o[nt][0] * inv0 * dd0, o[nt][1] * inv0 * dd1);
        float2 r1 = make_float2(o[nt][2] * inv1 * dd0, o[nt][3] * inv1 * dd1);
        *(float2*)&out[row0 * EMB + h * HD + d0] = r0;
        *(float2*)&out[row1 * EMB + h * HD + d0] = r1;
    }
}

// ---------------------------------------------------------------------------
extern "C" void kernel_launch(void* const* d_in, const int* in_sizes, int n_in,
                              void* d_out, int out_size) {
    (void)in_sizes; (void)n_in; (void)out_size;
    const float* hidden = (const float*)d_in[0];   // [1,4096,1024]
    const float* W      = (const float*)d_in[1];   // [3072,1024]
    const float* bias   = (const float*)d_in[2];   // [3072]
    const float* trace  = (const float*)d_in[3];   // [16,64,64]
    float* out = (float*)d_out;                    // [1,4096,1024]

    uint2* dA; cudaGetSymbolAddress((void**)&dA, g_A_split);
    uint2* dW; cudaGetSymbolAddress((void**)&dW, g_W_split);

    // prep: split inputs
    {
        int n4a = SEQ * EMB / 4;
        split_kernel<<<(n4a + 255) / 256, 256>>>((const float4*)hidden, dA, n4a);
        int n4w = QKV_COLS * EMB / 4;
        split_kernel<<<(n4w + 255) / 256, 256>>>((const float4*)W, dW, n4w);
    }

    static int inited = 0;
    if (!inited) {
        cudaFuncSetAttribute(qkv_gemm_mma,
                             cudaFuncAttributeMaxDynamicSharedMemorySize, 81920);
        cudaFuncSetAttribute(attn_mma,
                             cudaFuncAttributeMaxDynamicSharedMemorySize, 110592);
        inited = 1;
    }

    qkv_gemm_mma<<<dim3(QKV_COLS / 128, SEQ / 128), 256, 81920>>>(bias);
    vT_kernel<<<(NH * HD * (SEQ / 2)) / 256, 256>>>();
    attn_mma<<<dim3(SEQ / 128, NH), 256, 110592>>>(trace, out);
}

// round 11
// speedup vs baseline: 3.7717x; 1.3832x over previous
#include <cuda_runtime.h>
#include <cuda_fp16.h>
#include <stdint.h>

#define SEQ 4096
#define EMB 1024
#define NH 16
#define HD 64
#define QKV_COLS 3072
#define QKV_C2 1536          // uint2 columns of the split qkv

// ---- static device scratch (no runtime allocation) ----
__device__ __align__(16) uint2 g_A_split[SEQ * (EMB / 2)];        // [4096][512]
__device__ __align__(16) uint2 g_W_split[QKV_COLS * (EMB / 2)];   // [3072][512]
__device__ __align__(16) uint2 g_qkv_split[SEQ * QKV_C2];         // [4096][1536]
__device__ __align__(16) uint2 g_vT_split[NH * HD * (SEQ / 2)];   // [16][64][2048]

// ---------------------------------------------------------------------------
// helpers
// ---------------------------------------------------------------------------
// Split (x0,x1) fp32 -> {fp16-pair hi, fp16-pair lo}. low halfword = x0.
// hi = RN(x), lo = RN(x - hi):  hi + lo represents x to ~2^-22.
__device__ __forceinline__ uint2 split2(float x0, float x1) {
    uint32_t hp, lp;
    asm("cvt.rn.f16x2.f32 %0, %1, %2;" : "=r"(hp) : "f"(x1), "f"(x0));
    __half2 hb = *reinterpret_cast<__half2*>(&hp);
    float2 back = __half22float2(hb);
    float r0 = x0 - back.x;
    float r1 = x1 - back.y;
    asm("cvt.rn.f16x2.f32 %0, %1, %2;" : "=r"(lp) : "f"(r1), "f"(r0));
    return make_uint2(hp, lp);
}

// D(16x8,f32) += A(16x16,f16) * B(16x8,f16)
__device__ __forceinline__ void mma16816(float* d, const uint32_t* a,
                                         uint32_t b0, uint32_t b1) {
    asm volatile(
        "mma.sync.aligned.m16n8k16.row.col.f32.f16.f16.f32 "
        "{%0,%1,%2,%3}, {%4,%5,%6,%7}, {%8,%9}, {%0,%1,%2,%3};"
        : "+f"(d[0]), "+f"(d[1]), "+f"(d[2]), "+f"(d[3])
        : "r"(a[0]), "r"(a[1]), "r"(a[2]), "r"(a[3]), "r"(b0), "r"(b1));
}

// ---------------------------------------------------------------------------
// Prep: fp32 -> split-fp16 pairs
// ---------------------------------------------------------------------------
__global__ void split_kernel(const float4* __restrict__ src,
                             uint2* __restrict__ dst, int n4) {
    int i = blockIdx.x * blockDim.x + threadIdx.x;
    if (i >= n4) return;
    float4 v = src[i];
    dst[2 * i]     = split2(v.x, v.y);
    dst[2 * i + 1] = split2(v.z, v.w);
}

// ---------------------------------------------------------------------------
// Kernel 1: QKV GEMM, fp16x2 mma.  C[4096,3072] = A @ W^T + bias
//   Passes: a_hi*w_hi + a_lo*w_hi = a*w_hi  (dropped a*w_lo ~ 2^-12 rel).
//   128x128x32 tile, 256 threads; warp grid 4(M)x2(N), warp tile 32x64.
//   Q columns (n < 1024) pre-scaled by 1/sqrt(64)=0.125.
// ---------------------------------------------------------------------------
#define G_AS 20   // smem row stride in uint2 (160B = 40 banks ≡ 8 mod 32)

__global__ __launch_bounds__(256)
void qkv_gemm_mma(const float* __restrict__ bias) {
    extern __shared__ uint2 smg[];
    uint2* As = smg;                       // [2][128*G_AS]
    uint2* Bs = smg + 2 * 128 * G_AS;      // [2][128*G_AS]
    uint4* As4 = reinterpret_cast<uint4*>(As);
    uint4* Bs4 = reinterpret_cast<uint4*>(Bs);

    const int t = threadIdx.x;
    const int warp = t >> 5, lane = t & 31;
    const int g = lane >> 2, tq = lane & 3;
    const int wm = warp & 3;      // row warp
    const int wn = warp >> 2;     // col warp
    const int bm = blockIdx.y * 128;
    const int bn = blockIdx.x * 128;

    const uint4* A4 = reinterpret_cast<const uint4*>(g_A_split);
    const uint4* B4 = reinterpret_cast<const uint4*>(g_W_split);

    const int lr = t >> 3;       // loader row 0..31 (+32*i)
    const int lc = t & 7;        // loader uint4 col 0..7

    float acc[2][8][4];
    #pragma unroll
    for (int mt = 0; mt < 2; ++mt)
        #pragma unroll
        for (int nt = 0; nt < 8; ++nt)
            #pragma unroll
            for (int j = 0; j < 4; ++j) acc[mt][nt][j] = 0.f;

    uint4 pa[4], pb[4];
    // preload kt = 0
    #pragma unroll
    for (int i = 0; i < 4; ++i) {
        int r = lr + i * 32;
        pa[i] = A4[(bm + r) * 256 + lc];
        pb[i] = B4[(bn + r) * 256 + lc];
    }
    #pragma unroll
    for (int i = 0; i < 4; ++i) {
        int r = lr + i * 32;
        As4[r * 10 + lc] = pa[i];
        Bs4[r * 10 + lc] = pb[i];
    }
    __syncthreads();

    for (int kt = 0; kt < 32; ++kt) {
        const int cur = kt & 1;
        if (kt < 31) {
            #pragma unroll
            for (int i = 0; i < 4; ++i) {
                int r = lr + i * 32;
                pa[i] = A4[(bm + r) * 256 + (kt + 1) * 8 + lc];
                pb[i] = B4[(bn + r) * 256 + (kt + 1) * 8 + lc];
            }
        }
        const uint2* Ab = As + cur * (128 * G_AS);
        const uint2* Bb = Bs + cur * (128 * G_AS);

        #pragma unroll
        for (int ks = 0; ks < 2; ++ks) {
            const int k2b = ks * 8;
            uint32_t ah[2][4], al[2][4];
            #pragma unroll
            for (int mt = 0; mt < 2; ++mt) {
                int row = wm * 32 + mt * 16 + g;
                uint2 f0 = Ab[row * G_AS + k2b + tq];
                uint2 f1 = Ab[(row + 8) * G_AS + k2b + tq];
                uint2 f2 = Ab[row * G_AS + k2b + tq + 4];
                uint2 f3 = Ab[(row + 8) * G_AS + k2b + tq + 4];
                ah[mt][0] = f0.x; al[mt][0] = f0.y;
                ah[mt][1] = f1.x; al[mt][1] = f1.y;
                ah[mt][2] = f2.x; al[mt][2] = f2.y;
                ah[mt][3] = f3.x; al[mt][3] = f3.y;
            }
            uint32_t bh[8][2];
            #pragma unroll
            for (int nt = 0; nt < 8; ++nt) {
                int col = wn * 64 + nt * 8 + g;
                uint2 e0 = Bb[col * G_AS + k2b + tq];
                uint2 e1 = Bb[col * G_AS + k2b + tq + 4];
                bh[nt][0] = e0.x;
                bh[nt][1] = e1.x;
            }
            #pragma unroll
            for (int mt = 0; mt < 2; ++mt)
                #pragma unroll
                for (int nt = 0; nt < 8; ++nt) {
                    mma16816(acc[mt][nt], ah[mt], bh[nt][0], bh[nt][1]);
                    mma16816(acc[mt][nt], al[mt], bh[nt][0], bh[nt][1]);
                }
        }
        if (kt < 31) {
            uint4* Ad = As4 + (cur ^ 1) * (128 * G_AS / 2);
            uint4* Bd = Bs4 + (cur ^ 1) * (128 * G_AS / 2);
            #pragma unroll
            for (int i = 0; i < 4; ++i) {
                int r = lr + i * 32;
                Ad[r * 10 + lc] = pa[i];
                Bd[r * 10 + lc] = pb[i];
            }
        }
        __syncthreads();
    }

    // epilogue: + bias, Q scale, split to fp16 pairs, store
    const float scale = (bn < EMB) ? 0.125f : 1.0f;
    #pragma unroll
    for (int mt = 0; mt < 2; ++mt) {
        int r0 = bm + wm * 32 + mt * 16 + g;
        #pragma unroll
        for (int nt = 0; nt < 8; ++nt) {
            int col0 = bn + wn * 64 + nt * 8 + 2 * tq;
            float b0 = bias[col0], b1 = bias[col0 + 1];
            float v00 = (acc[mt][nt][0] + b0) * scale;
            float v01 = (acc[mt][nt][1] + b1) * scale;
            float v10 = (acc[mt][nt][2] + b0) * scale;
            float v11 = (acc[mt][nt][3] + b1) * scale;
            g_qkv_split[r0 * QKV_C2 + (col0 >> 1)]       = split2(v00, v01);
            g_qkv_split[(r0 + 8) * QKV_C2 + (col0 >> 1)] = split2(v10, v11);
        }
    }
}

// ---------------------------------------------------------------------------
// Kernel 2: V transpose  qkv_split V region -> vT_split[h][d][m-pair]
//   V region = uint2 columns [1024,1536).
// ---------------------------------------------------------------------------
__global__ void vT_kernel() {
    int i = blockIdx.x * 256 + threadIdx.x;       // 16*64*2048 total
    int m2 = i & 2047;
    int d  = (i >> 11) & 63;
    int h  = i >> 17;
    int col = 1024 + h * 32 + (d >> 1);
    uint2 p0 = g_qkv_split[(2 * m2) * QKV_C2 + col];
    uint2 p1 = g_qkv_split[(2 * m2 + 1) * QKV_C2 + col];
    uint32_t sh = (d & 1) ? 16 : 0;
    uint32_t h0 = (p0.x >> sh) & 0xffffu;
    uint32_t h1 = (p1.x >> sh) & 0xffffu;
    uint32_t l0 = (p0.y >> sh) & 0xffffu;
    uint32_t l1 = (p1.y >> sh) & 0xffffu;
    g_vT_split[((h * 64 + d) << 11) + m2] = make_uint2(h0 | (h1 << 16), l0 | (l1 << 16));
}

// ---------------------------------------------------------------------------
// Kernel 3: flash attention, fp16x2 mma + fused Hebbian diagonal.
//   S: q_hi*k_hi + q_lo*k_hi = q*k_hi;  PV: p_hi*v_hi + p_lo*v_hi = p*v_hi.
//   Block = (q-tile 128, head). 8 warps x 16 q-rows. KV tiles of 64.
// ---------------------------------------------------------------------------
#define ABK 64
#define KV_S 36    // smem row stride in uint2 (288B = 72 banks ≡ 8 mod 32)

__global__ __launch_bounds__(256)
void attn_mma(const float* __restrict__ trace, float* __restrict__ out) {
    extern __shared__ uint2 sma[];
    uint2* Qs = sma;                           // [128][KV_S]
    uint2* Ks = sma + 128 * KV_S;              // [2][64][KV_S]
    uint2* Vs = Ks + 2 * 64 * KV_S;            // [2][64][KV_S]
    uint4* Qs4 = reinterpret_cast<uint4*>(Qs);
    uint4* Ks4 = reinterpret_cast<uint4*>(Ks);
    uint4* Vs4 = reinterpret_cast<uint4*>(Vs);

    const int t = threadIdx.x;
    const int warp = t >> 5, lane = t & 31;
    const int g = lane >> 2, tq = lane & 3;
    const int h = blockIdx.y;
    const int q0 = blockIdx.x * 128;

    const uint4* G4  = reinterpret_cast<const uint4*>(g_qkv_split);   // row = 768 uint4
    const uint4* VT4 = reinterpret_cast<const uint4*>(g_vT_split);    // row = 1024 uint4

    const int lr = t >> 4;    // 0..15
    const int lc = t & 15;    // uint4 col 0..15

    // ---- load Q tile to smem ----
    #pragma unroll
    for (int i = 0; i < 8; ++i) {
        int r = lr + i * 16;
        Qs4[r * 18 + lc] = G4[(q0 + r) * 768 + h * 16 + lc];
    }
    __syncthreads();

    // ---- Q fragments -> registers ----
    const int qr = warp * 16;
    uint32_t qh[4][4], ql[4][4];
    #pragma unroll
    for (int ks = 0; ks < 4; ++ks) {
        uint2 f0 = Qs[(qr + g) * KV_S + 8 * ks + tq];
        uint2 f1 = Qs[(qr + g + 8) * KV_S + 8 * ks + tq];
        uint2 f2 = Qs[(qr + g) * KV_S + 8 * ks + tq + 4];
        uint2 f3 = Qs[(qr + g + 8) * KV_S + 8 * ks + tq + 4];
        qh[ks][0] = f0.x; ql[ks][0] = f0.y;
        qh[ks][1] = f1.x; ql[ks][1] = f1.y;
        qh[ks][2] = f2.x; ql[ks][2] = f2.y;
        qh[ks][3] = f3.x; ql[ks][3] = f3.y;
    }

    // ---- preload KV tile 0 ----
    uint4 pk[4], pv[4];
    #pragma unroll
    for (int i = 0; i < 4; ++i) {
        int r = lr + i * 16;
        pk[i] = G4[r * 768 + 256 + h * 16 + lc];
        pv[i] = VT4[(h * 64 + r) * 1024 + lc];
    }
    #pragma unroll
    for (int i = 0; i < 4; ++i) {
        int r = lr + i * 16;
        Ks4[r * 18 + lc] = pk[i];
        Vs4[r * 18 + lc] = pv[i];
    }
    __syncthreads();

    float m0 = -1e30f, m1 = -1e30f, l0 = 0.f, l1 = 0.f;
    float o[8][4];
    #pragma unroll
    for (int nt = 0; nt < 8; ++nt)
        #pragma unroll
        for (int j = 0; j < 4; ++j) o[nt][j] = 0.f;

    for (int it = 0; it < SEQ / ABK; ++it) {
        const int cur = it & 1;
        if (it < SEQ / ABK - 1) {
            int kv0 = (it + 1) * ABK;
            #pragma unroll
            for (int i = 0; i < 4; ++i) {
                int r = lr + i * 16;
                pk[i] = G4[(kv0 + r) * 768 + 256 + h * 16 + lc];
                pv[i] = VT4[(h * 64 + r) * 1024 + (it + 1) * 16 + lc];
            }
        }
        const uint2* Kb = Ks + cur * (64 * KV_S);
        const uint2* Vb = Vs + cur * (64 * KV_S);

        // ---- S = Q @ K_hi^T ----
        float s[8][4];
        #pragma unroll
        for (int nt = 0; nt < 8; ++nt)
            #pragma unroll
            for (int j = 0; j < 4; ++j) s[nt][j] = 0.f;

        #pragma unroll
        for (int ks = 0; ks < 4; ++ks) {
            #pragma unroll
            for (int nt = 0; nt < 8; ++nt) {
                int n = nt * 8 + g;
                uint2 e0 = Kb[n * KV_S + 8 * ks + tq];
                uint2 e1 = Kb[n * KV_S + 8 * ks + tq + 4];
                mma16816(s[nt], qh[ks], e0.x, e1.x);
                mma16816(s[nt], ql[ks], e0.x, e1.x);
            }
        }

        // ---- online softmax (quad reduction; rows g and g+8) ----
        float rm0 = -1e30f, rm1 = -1e30f;
        #pragma unroll
        for (int nt = 0; nt < 8; ++nt) {
            rm0 = fmaxf(rm0, fmaxf(s[nt][0], s[nt][1]));
            rm1 = fmaxf(rm1, fmaxf(s[nt][2], s[nt][3]));
        }
        #pragma unroll
        for (int w = 1; w < 4; w <<= 1) {
            rm0 = fmaxf(rm0, __shfl_xor_sync(0xffffffffu, rm0, w));
            rm1 = fmaxf(rm1, __shfl_xor_sync(0xffffffffu, rm1, w));
        }
        float n0 = fmaxf(m0, rm0), n1 = fmaxf(m1, rm1);
        float a0 = __expf(m0 - n0), a1 = __expf(m1 - n1);
        m0 = n0; m1 = n1;
        float rs0 = 0.f, rs1 = 0.f;
        #pragma unroll
        for (int nt = 0; nt < 8; ++nt) {
            s[nt][0] = __expf(s[nt][0] - n0);
            s[nt][1] = __expf(s[nt][1] - n0);
            s[nt][2] = __expf(s[nt][2] - n1);
            s[nt][3] = __expf(s[nt][3] - n1);
            rs0 += s[nt][0] + s[nt][1];
            rs1 += s[nt][2] + s[nt][3];
        }
        #pragma unroll
        for (int w = 1; w < 4; w <<= 1) {
            rs0 += __shfl_xor_sync(0xffffffffu, rs0, w);
            rs1 += __shfl_xor_sync(0xffffffffu, rs1, w);
        }
        l0 = l0 * a0 + rs0;
        l1 = l1 * a1 + rs1;
        #pragma unroll
        for (int nt = 0; nt < 8; ++nt) {
            o[nt][0] *= a0; o[nt][1] *= a0;
            o[nt][2] *= a1; o[nt][3] *= a1;
        }

        // ---- O += P @ V_hi  (P split into hi+lo fp16; c-layout == a-layout) ----
        #pragma unroll
        for (int ks = 0; ks < 4; ++ks) {
            uint32_t ph[4], pl[4];
            uint2 u;
            u = split2(s[2 * ks][0], s[2 * ks][1]);         ph[0] = u.x; pl[0] = u.y;
            u = split2(s[2 * ks][2], s[2 * ks][3]);         ph[1] = u.x; pl[1] = u.y;
            u = split2(s[2 * ks + 1][0], s[2 * ks + 1][1]); ph[2] = u.x; pl[2] = u.y;
            u = split2(s[2 * ks + 1][2], s[2 * ks + 1][3]); ph[3] = u.x; pl[3] = u.y;
            #pragma unroll
            for (int nt = 0; nt < 8; ++nt) {
                int n = nt * 8 + g;   // d index
                uint2 e0 = Vb[n * KV_S + 8 * ks + tq];
                uint2 e1 = Vb[n * KV_S + 8 * ks + tq + 4];
                mma16816(o[nt], ph, e0.x, e1.x);
                mma16816(o[nt], pl, e0.x, e1.x);
            }
        }

        if (it < SEQ / ABK - 1) {
            uint4* Kd = Ks4 + (cur ^ 1) * (64 * KV_S / 2);
            uint4* Vd = Vs4 + (cur ^ 1) * (64 * KV_S / 2);
            #pragma unroll
            for (int i = 0; i < 4; ++i) {
                int r = lr + i * 16;
                Kd[r * 18 + lc] = pk[i];
                Vd[r * 18 + lc] = pv[i];
            }
        }
        __syncthreads();
    }

    // ---- epilogue: 1/l, Hebbian diag, store ----
    float inv0 = 1.f / l0, inv1 = 1.f / l1;
    int row0 = q0 + qr + g, row1 = row0 + 8;
    #pragma unroll
    for (int nt = 0; nt < 8; ++nt) {
        int d0 = nt * 8 + 2 * tq;
        float dd0 = trace[h * 4096 + d0 * 65];
        float dd1 = trace[h * 4096 + (d0 + 1) * 65];
        float2 r0 = make_float2(o[nt][0] * inv0 * dd0, o[nt][1] * inv0 * dd1);
        float2 r1 = make_float2(o[nt][2] * inv1 * dd0, o[nt][3] * inv1 * dd1);
        *(float2*)&out[row0 * EMB + h * HD + d0] = r0;
        *(float2*)&out[row1 * EMB + h * HD + d0] = r1;
    }
}

// ---------------------------------------------------------------------------
extern "C" void kernel_launch(void* const* d_in, const int* in_sizes, int n_in,
                              void* d_out, int out_size) {
    (void)in_sizes; (void)n_in; (void)out_size;
    const float* hidden = (const float*)d_in[0];   // [1,4096,1024]
    const float* W      = (const float*)d_in[1];   // [3072,1024]
    const float* bias   = (const float*)d_in[2];   // [3072]
    const float* trace  = (const float*)d_in[3];   // [16,64,64]
    float* out = (float*)d_out;                    // [1,4096,1024]

    uint2* dA; cudaGetSymbolAddress((void**)&dA, g_A_split);
    uint2* dW; cudaGetSymbolAddress((void**)&dW, g_W_split);

    // prep: split inputs
    {
        int n4a = SEQ * EMB / 4;
        split_kernel<<<(n4a + 255) / 256, 256>>>((const float4*)hidden, dA, n4a);
        int n4w = QKV_COLS * EMB / 4;
        split_kernel<<<(n4w + 255) / 256, 256>>>((const float4*)W, dW, n4w);
    }

    static int inited = 0;
    if (!inited) {
        cudaFuncSetAttribute(qkv_gemm_mma,
                             cudaFuncAttributeMaxDynamicSharedMemorySize, 81920);
        cudaFuncSetAttribute(attn_mma,
                             cudaFuncAttributeMaxDynamicSharedMemorySize, 110592);
        inited = 1;
    }

    qkv_gemm_mma<<<dim3(QKV_COLS / 128, SEQ / 128), 256, 81920>>>(bias);
    vT_kernel<<<(NH * HD * (SEQ / 2)) / 256, 256>>>();
    attn_mma<<<dim3(SEQ / 128, NH), 256, 110592>>>(trace, out);
}

// round 12
// speedup vs baseline: 3.9608x; 1.0501x over previous
#include <cuda_runtime.h>
#include <cuda_fp16.h>
#include <stdint.h>

#define SEQ 4096
#define EMB 1024
#define NH 16
#define HD 64
#define QKV_COLS 3072
#define QKV_C2 1536          // uint2 columns of the split qkv

// ---- static device scratch (no runtime allocation) ----
__device__ __align__(16) uint2 g_A_split[SEQ * (EMB / 2)];        // [4096][512]
__device__ __align__(16) uint2 g_W_split[QKV_COLS * (EMB / 2)];   // [3072][512]
__device__ __align__(16) uint2 g_qkv_split[SEQ * QKV_C2];         // [4096][1536]
__device__ __align__(16) uint2 g_vT_split[NH * HD * (SEQ / 2)];   // [16][64][2048]

// ---------------------------------------------------------------------------
// helpers
// ---------------------------------------------------------------------------
// Split (x0,x1) fp32 -> {fp16-pair hi, fp16-pair lo}. low halfword = x0.
__device__ __forceinline__ uint2 split2(float x0, float x1) {
    uint32_t hp, lp;
    asm("cvt.rn.f16x2.f32 %0, %1, %2;" : "=r"(hp) : "f"(x1), "f"(x0));
    __half2 hb = *reinterpret_cast<__half2*>(&hp);
    float2 back = __half22float2(hb);
    float r0 = x0 - back.x;
    float r1 = x1 - back.y;
    asm("cvt.rn.f16x2.f32 %0, %1, %2;" : "=r"(lp) : "f"(r1), "f"(r0));
    return make_uint2(hp, lp);
}

// Pack (x0,x1) fp32 -> fp16-pair (RN), low halfword = x0.
__device__ __forceinline__ uint32_t pack2(float x0, float x1) {
    uint32_t hp;
    asm("cvt.rn.f16x2.f32 %0, %1, %2;" : "=r"(hp) : "f"(x1), "f"(x0));
    return hp;
}

// D(16x8,f32) += A(16x16,f16) * B(16x8,f16)
__device__ __forceinline__ void mma16816(float* d, const uint32_t* a,
                                         uint32_t b0, uint32_t b1) {
    asm volatile(
        "mma.sync.aligned.m16n8k16.row.col.f32.f16.f16.f32 "
        "{%0,%1,%2,%3}, {%4,%5,%6,%7}, {%8,%9}, {%0,%1,%2,%3};"
        : "+f"(d[0]), "+f"(d[1]), "+f"(d[2]), "+f"(d[3])
        : "r"(a[0]), "r"(a[1]), "r"(a[2]), "r"(a[3]), "r"(b0), "r"(b1));
}

// ---------------------------------------------------------------------------
// Prep: fp32 -> split-fp16 pairs
// ---------------------------------------------------------------------------
__global__ void split_kernel(const float4* __restrict__ src,
                             uint2* __restrict__ dst, int n4) {
    int i = blockIdx.x * blockDim.x + threadIdx.x;
    if (i >= n4) return;
    float4 v = src[i];
    dst[2 * i]     = split2(v.x, v.y);
    dst[2 * i + 1] = split2(v.z, v.w);
}

// ---------------------------------------------------------------------------
// Kernel 1: QKV GEMM, fp16x2 mma.  C[4096,3072] = A @ W^T + bias
//   Passes: a_hi*w_hi + a_lo*w_hi = a*w_hi.
//   128x128x32 tile, 256 threads; warp grid 4(M)x2(N), warp tile 32x64.
//   Q columns (n < 1024) pre-scaled by 1/sqrt(64)=0.125.
// ---------------------------------------------------------------------------
#define G_AS 20   // smem row stride in uint2 (160B = 40 banks ≡ 8 mod 32)

__global__ __launch_bounds__(256)
void qkv_gemm_mma(const float* __restrict__ bias) {
    extern __shared__ uint2 smg[];
    uint2* As = smg;                       // [2][128*G_AS]
    uint2* Bs = smg + 2 * 128 * G_AS;      // [2][128*G_AS]
    uint4* As4 = reinterpret_cast<uint4*>(As);
    uint4* Bs4 = reinterpret_cast<uint4*>(Bs);

    const int t = threadIdx.x;
    const int warp = t >> 5, lane = t & 31;
    const int g = lane >> 2, tq = lane & 3;
    const int wm = warp & 3;      // row warp
    const int wn = warp >> 2;     // col warp
    const int bm = blockIdx.y * 128;
    const int bn = blockIdx.x * 128;

    const uint4* A4 = reinterpret_cast<const uint4*>(g_A_split);
    const uint4* B4 = reinterpret_cast<const uint4*>(g_W_split);

    const int lr = t >> 3;       // loader row 0..31 (+32*i)
    const int lc = t & 7;        // loader uint4 col 0..7

    float acc[2][8][4];
    #pragma unroll
    for (int mt = 0; mt < 2; ++mt)
        #pragma unroll
        for (int nt = 0; nt < 8; ++nt)
            #pragma unroll
            for (int j = 0; j < 4; ++j) acc[mt][nt][j] = 0.f;

    uint4 pa[4], pb[4];
    // preload kt = 0
    #pragma unroll
    for (int i = 0; i < 4; ++i) {
        int r = lr + i * 32;
        pa[i] = A4[(bm + r) * 256 + lc];
        pb[i] = B4[(bn + r) * 256 + lc];
    }
    #pragma unroll
    for (int i = 0; i < 4; ++i) {
        int r = lr + i * 32;
        As4[r * 10 + lc] = pa[i];
        Bs4[r * 10 + lc] = pb[i];
    }
    __syncthreads();

    for (int kt = 0; kt < 32; ++kt) {
        const int cur = kt & 1;
        if (kt < 31) {
            #pragma unroll
            for (int i = 0; i < 4; ++i) {
                int r = lr + i * 32;
                pa[i] = A4[(bm + r) * 256 + (kt + 1) * 8 + lc];
                pb[i] = B4[(bn + r) * 256 + (kt + 1) * 8 + lc];
            }
        }
        const uint2* Ab = As + cur * (128 * G_AS);
        const uint2* Bb = Bs + cur * (128 * G_AS);

        #pragma unroll
        for (int ks = 0; ks < 2; ++ks) {
            const int k2b = ks * 8;
            uint32_t ah[2][4], al[2][4];
            #pragma unroll
            for (int mt = 0; mt < 2; ++mt) {
                int row = wm * 32 + mt * 16 + g;
                uint2 f0 = Ab[row * G_AS + k2b + tq];
                uint2 f1 = Ab[(row + 8) * G_AS + k2b + tq];
                uint2 f2 = Ab[row * G_AS + k2b + tq + 4];
                uint2 f3 = Ab[(row + 8) * G_AS + k2b + tq + 4];
                ah[mt][0] = f0.x; al[mt][0] = f0.y;
                ah[mt][1] = f1.x; al[mt][1] = f1.y;
                ah[mt][2] = f2.x; al[mt][2] = f2.y;
                ah[mt][3] = f3.x; al[mt][3] = f3.y;
            }
            uint32_t bh[8][2];
            #pragma unroll
            for (int nt = 0; nt < 8; ++nt) {
                int col = wn * 64 + nt * 8 + g;
                uint2 e0 = Bb[col * G_AS + k2b + tq];
                uint2 e1 = Bb[col * G_AS + k2b + tq + 4];
                bh[nt][0] = e0.x;
                bh[nt][1] = e1.x;
            }
            #pragma unroll
            for (int mt = 0; mt < 2; ++mt)
                #pragma unroll
                for (int nt = 0; nt < 8; ++nt) {
                    mma16816(acc[mt][nt], ah[mt], bh[nt][0], bh[nt][1]);
                    mma16816(acc[mt][nt], al[mt], bh[nt][0], bh[nt][1]);
                }
        }
        if (kt < 31) {
            uint4* Ad = As4 + (cur ^ 1) * (128 * G_AS / 2);
            uint4* Bd = Bs4 + (cur ^ 1) * (128 * G_AS / 2);
            #pragma unroll
            for (int i = 0; i < 4; ++i) {
                int r = lr + i * 32;
                Ad[r * 10 + lc] = pa[i];
                Bd[r * 10 + lc] = pb[i];
            }
        }
        __syncthreads();
    }

    // epilogue: + bias, Q scale, split to fp16 pairs, store
    const float scale = (bn < EMB) ? 0.125f : 1.0f;
    #pragma unroll
    for (int mt = 0; mt < 2; ++mt) {
        int r0 = bm + wm * 32 + mt * 16 + g;
        #pragma unroll
        for (int nt = 0; nt < 8; ++nt) {
            int col0 = bn + wn * 64 + nt * 8 + 2 * tq;
            float b0 = bias[col0], b1 = bias[col0 + 1];
            float v00 = (acc[mt][nt][0] + b0) * scale;
            float v01 = (acc[mt][nt][1] + b1) * scale;
            float v10 = (acc[mt][nt][2] + b0) * scale;
            float v11 = (acc[mt][nt][3] + b1) * scale;
            g_qkv_split[r0 * QKV_C2 + (col0 >> 1)]       = split2(v00, v01);
            g_qkv_split[(r0 + 8) * QKV_C2 + (col0 >> 1)] = split2(v10, v11);
        }
    }
}

// ---------------------------------------------------------------------------
// Kernel 2: V transpose  qkv_split V region -> vT_split[h][d][m-pair]
//   V region = uint2 columns [1024,1536).
// ---------------------------------------------------------------------------
__global__ void vT_kernel() {
    int i = blockIdx.x * 256 + threadIdx.x;       // 16*64*2048 total
    int m2 = i & 2047;
    int d  = (i >> 11) & 63;
    int h  = i >> 17;
    int col = 1024 + h * 32 + (d >> 1);
    uint2 p0 = g_qkv_split[(2 * m2) * QKV_C2 + col];
    uint2 p1 = g_qkv_split[(2 * m2 + 1) * QKV_C2 + col];
    uint32_t sh = (d & 1) ? 16 : 0;
    uint32_t h0 = (p0.x >> sh) & 0xffffu;
    uint32_t h1 = (p1.x >> sh) & 0xffffu;
    uint32_t l0 = (p0.y >> sh) & 0xffffu;
    uint32_t l1 = (p1.y >> sh) & 0xffffu;
    g_vT_split[((h * 64 + d) << 11) + m2] = make_uint2(h0 | (h1 << 16), l0 | (l1 << 16));
}

// ---------------------------------------------------------------------------
// Kernel 3: flash attention, fp16 mma + fused Hebbian diagonal.
//   S: q_hi*k_hi + q_lo*k_hi = q*k_hi  (2 passes).
//   PV: SINGLE pass with quantized P; the softmax normalizer l is accumulated
//       from the SAME fp16-rounded p values, so O/l stays an exactly
//       normalized convex combination (weight-perturbation error only).
//   Block = (q-tile 128, head). 8 warps x 16 q-rows. KV tiles of 64.
// ---------------------------------------------------------------------------
#define ABK 64
#define KV_S 36    // smem row stride in uint2 (288B = 72 banks ≡ 8 mod 32)

__global__ __launch_bounds__(256)
void attn_mma(const float* __restrict__ trace, float* __restrict__ out) {
    extern __shared__ uint2 sma[];
    uint2* Qs = sma;                           // [128][KV_S]
    uint2* Ks = sma + 128 * KV_S;              // [2][64][KV_S]
    uint2* Vs = Ks + 2 * 64 * KV_S;            // [2][64][KV_S]
    uint4* Qs4 = reinterpret_cast<uint4*>(Qs);
    uint4* Ks4 = reinterpret_cast<uint4*>(Ks);
    uint4* Vs4 = reinterpret_cast<uint4*>(Vs);

    const int t = threadIdx.x;
    const int warp = t >> 5, lane = t & 31;
    const int g = lane >> 2, tq = lane & 3;
    const int h = blockIdx.y;
    const int q0 = blockIdx.x * 128;

    const uint4* G4  = reinterpret_cast<const uint4*>(g_qkv_split);   // row = 768 uint4
    const uint4* VT4 = reinterpret_cast<const uint4*>(g_vT_split);    // row = 1024 uint4

    const int lr = t >> 4;    // 0..15
    const int lc = t & 15;    // uint4 col 0..15

    // ---- load Q tile to smem ----
    #pragma unroll
    for (int i = 0; i < 8; ++i) {
        int r = lr + i * 16;
        Qs4[r * 18 + lc] = G4[(q0 + r) * 768 + h * 16 + lc];
    }
    __syncthreads();

    // ---- Q fragments -> registers ----
    const int qr = warp * 16;
    uint32_t qh[4][4], ql[4][4];
    #pragma unroll
    for (int ks = 0; ks < 4; ++ks) {
        uint2 f0 = Qs[(qr + g) * KV_S + 8 * ks + tq];
        uint2 f1 = Qs[(qr + g + 8) * KV_S + 8 * ks + tq];
        uint2 f2 = Qs[(qr + g) * KV_S + 8 * ks + tq + 4];
        uint2 f3 = Qs[(qr + g + 8) * KV_S + 8 * ks + tq + 4];
        qh[ks][0] = f0.x; ql[ks][0] = f0.y;
        qh[ks][1] = f1.x; ql[ks][1] = f1.y;
        qh[ks][2] = f2.x; ql[ks][2] = f2.y;
        qh[ks][3] = f3.x; ql[ks][3] = f3.y;
    }

    // ---- preload KV tile 0 ----
    uint4 pk[4], pv[4];
    #pragma unroll
    for (int i = 0; i < 4; ++i) {
        int r = lr + i * 16;
        pk[i] = G4[r * 768 + 256 + h * 16 + lc];
        pv[i] = VT4[(h * 64 + r) * 1024 + lc];
    }
    #pragma unroll
    for (int i = 0; i < 4; ++i) {
        int r = lr + i * 16;
        Ks4[r * 18 + lc] = pk[i];
        Vs4[r * 18 + lc] = pv[i];
    }
    __syncthreads();

    float m0 = -1e30f, m1 = -1e30f, l0 = 0.f, l1 = 0.f;
    float o[8][4];
    #pragma unroll
    for (int nt = 0; nt < 8; ++nt)
        #pragma unroll
        for (int j = 0; j < 4; ++j) o[nt][j] = 0.f;

    for (int it = 0; it < SEQ / ABK; ++it) {
        const int cur = it & 1;
        if (it < SEQ / ABK - 1) {
            int kv0 = (it + 1) * ABK;
            #pragma unroll
            for (int i = 0; i < 4; ++i) {
                int r = lr + i * 16;
                pk[i] = G4[(kv0 + r) * 768 + 256 + h * 16 + lc];
                pv[i] = VT4[(h * 64 + r) * 1024 + (it + 1) * 16 + lc];
            }
        }
        const uint2* Kb = Ks + cur * (64 * KV_S);
        const uint2* Vb = Vs + cur * (64 * KV_S);

        // ---- S = Q @ K_hi^T ----
        float s[8][4];
        #pragma unroll
        for (int nt = 0; nt < 8; ++nt)
            #pragma unroll
            for (int j = 0; j < 4; ++j) s[nt][j] = 0.f;

        #pragma unroll
        for (int ks = 0; ks < 4; ++ks) {
            #pragma unroll
            for (int nt = 0; nt < 8; ++nt) {
                int n = nt * 8 + g;
                uint2 e0 = Kb[n * KV_S + 8 * ks + tq];
                uint2 e1 = Kb[n * KV_S + 8 * ks + tq + 4];
                mma16816(s[nt], qh[ks], e0.x, e1.x);
                mma16816(s[nt], ql[ks], e0.x, e1.x);
            }
        }

        // ---- online softmax (quad reduction; rows g and g+8) ----
        float rm0 = -1e30f, rm1 = -1e30f;
        #pragma unroll
        for (int nt = 0; nt < 8; ++nt) {
            rm0 = fmaxf(rm0, fmaxf(s[nt][0], s[nt][1]));
            rm1 = fmaxf(rm1, fmaxf(s[nt][2], s[nt][3]));
        }
        #pragma unroll
        for (int w = 1; w < 4; w <<= 1) {
            rm0 = fmaxf(rm0, __shfl_xor_sync(0xffffffffu, rm0, w));
            rm1 = fmaxf(rm1, __shfl_xor_sync(0xffffffffu, rm1, w));
        }
        float n0 = fmaxf(m0, rm0), n1 = fmaxf(m1, rm1);
        float a0 = __expf(m0 - n0), a1 = __expf(m1 - n1);
        m0 = n0; m1 = n1;

        // exp, quantize P to fp16 ONCE, and accumulate l from the SAME
        // quantized values (consistent normalization).
        uint32_t ph[4][4];     // [ks][areg]
        float rs0 = 0.f, rs1 = 0.f;
        #pragma unroll
        for (int ks = 0; ks < 4; ++ks) {
            float p00 = __expf(s[2 * ks][0] - n0);
            float p01 = __expf(s[2 * ks][1] - n0);
            float p02 = __expf(s[2 * ks][2] - n1);
            float p03 = __expf(s[2 * ks][3] - n1);
            float p10 = __expf(s[2 * ks + 1][0] - n0);
            float p11 = __expf(s[2 * ks + 1][1] - n0);
            float p12 = __expf(s[2 * ks + 1][2] - n1);
            float p13 = __expf(s[2 * ks + 1][3] - n1);
            ph[ks][0] = pack2(p00, p01);
            ph[ks][1] = pack2(p02, p03);
            ph[ks][2] = pack2(p10, p11);
            ph[ks][3] = pack2(p12, p13);
            // back-convert quantized values for the normalizer
            float2 q00 = __half22float2(*reinterpret_cast<__half2*>(&ph[ks][0]));
            float2 q01 = __half22float2(*reinterpret_cast<__half2*>(&ph[ks][1]));
            float2 q10 = __half22float2(*reinterpret_cast<__half2*>(&ph[ks][2]));
            float2 q11 = __half22float2(*reinterpret_cast<__half2*>(&ph[ks][3]));
            rs0 += (q00.x + q00.y) + (q10.x + q10.y);
            rs1 += (q01.x + q01.y) + (q11.x + q11.y);
        }
        #pragma unroll
        for (int w = 1; w < 4; w <<= 1) {
            rs0 += __shfl_xor_sync(0xffffffffu, rs0, w);
            rs1 += __shfl_xor_sync(0xffffffffu, rs1, w);
        }
        l0 = l0 * a0 + rs0;
        l1 = l1 * a1 + rs1;
        #pragma unroll
        for (int nt = 0; nt < 8; ++nt) {
            o[nt][0] *= a0; o[nt][1] *= a0;
            o[nt][2] *= a1; o[nt][3] *= a1;
        }

        // ---- O += P_hi @ V_hi  (single pass) ----
        #pragma unroll
        for (int ks = 0; ks < 4; ++ks) {
            #pragma unroll
            for (int nt = 0; nt < 8; ++nt) {
                int n = nt * 8 + g;   // d index
                uint2 e0 = Vb[n * KV_S + 8 * ks + tq];
                uint2 e1 = Vb[n * KV_S + 8 * ks + tq + 4];
                mma16816(o[nt], ph[ks], e0.x, e1.x);
            }
        }

        if (it < SEQ / ABK - 1) {
            uint4* Kd = Ks4 + (cur ^ 1) * (64 * KV_S / 2);
            uint4* Vd = Vs4 + (cur ^ 1) * (64 * KV_S / 2);
            #pragma unroll
            for (int i = 0; i < 4; ++i) {
                int r = lr + i * 16;
                Kd[r * 18 + lc] = pk[i];
                Vd[r * 18 + lc] = pv[i];
            }
        }
        __syncthreads();
    }

    // ---- epilogue: 1/l, Hebbian diag, store ----
    float inv0 = 1.f / l0, inv1 = 1.f / l1;
    int row0 = q0 + qr + g, row1 = row0 + 8;
    #pragma unroll
    for (int nt = 0; nt < 8; ++nt) {
        int d0 = nt * 8 + 2 * tq;
        float dd0 = trace[h * 4096 + d0 * 65];
        float dd1 = trace[h * 4096 + (d0 + 1) * 65];
        float2 r0 = make_float2(o[nt][0] * inv0 * dd0, o[nt][1] * inv0 * dd1);
        float2 r1 = make_float2(o[nt][2] * inv1 * dd0, o[nt][3] * inv1 * dd1);
        *(float2*)&out[row0 * EMB + h * HD + d0] = r0;
        *(float2*)&out[row1 * EMB + h * HD + d0] = r1;
    }
}

// ---------------------------------------------------------------------------
extern "C" void kernel_launch(void* const* d_in, const int* in_sizes, int n_in,
                              void* d_out, int out_size) {
    (void)in_sizes; (void)n_in; (void)out_size;
    const float* hidden = (const float*)d_in[0];   // [1,4096,1024]
    const float* W      = (const float*)d_in[1];   // [3072,1024]
    const float* bias   = (const float*)d_in[2];   // [3072]
    const float* trace  = (const float*)d_in[3];   // [16,64,64]
    float* out = (float*)d_out;                    // [1,4096,1024]

    uint2* dA; cudaGetSymbolAddress((void**)&dA, g_A_split);
    uint2* dW; cudaGetSymbolAddress((void**)&dW, g_W_split);

    // prep: split inputs
    {
        int n4a = SEQ * EMB / 4;
        split_kernel<<<(n4a + 255) / 256, 256>>>((const float4*)hidden, dA, n4a);
        int n4w = QKV_COLS * EMB / 4;
        split_kernel<<<(n4w + 255) / 256, 256>>>((const float4*)W, dW, n4w);
    }

    static int inited = 0;
    if (!inited) {
        cudaFuncSetAttribute(qkv_gemm_mma,
                             cudaFuncAttributeMaxDynamicSharedMemorySize, 81920);
        cudaFuncSetAttribute(attn_mma,
                             cudaFuncAttributeMaxDynamicSharedMemorySize, 110592);
        inited = 1;
    }

    qkv_gemm_mma<<<dim3(QKV_COLS / 128, SEQ / 128), 256, 81920>>>(bias);
    vT_kernel<<<(NH * HD * (SEQ / 2)) / 256, 256>>>();
    attn_mma<<<dim3(SEQ / 128, NH), 256, 110592>>>(trace, out);
}

// round 13
// speedup vs baseline: 4.6091x; 1.1637x over previous
#include <cuda_runtime.h>
#include <cuda_fp16.h>
#include <stdint.h>

#define SEQ 4096
#define EMB 1024
#define NH 16
#define HD 64
#define QKV_COLS 3072
#define QKV_C2 1536          // uint2 columns of the split qkv

// Q pre-scale: 1/sqrt(64) * log2(e)  (softmax runs in exp2 domain)
#define QSCALE 0.1803368801111204f

// ---- static device scratch (no runtime allocation) ----
__device__ __align__(16) uint2    g_A_split[SEQ * (EMB / 2)];      // [4096][512]
__device__ __align__(16) uint2    g_W_split[QKV_COLS * (EMB / 2)]; // [3072][512]
__device__ __align__(16) uint2    g_qkv_split[SEQ * QKV_C2];       // Q region only used
__device__ __align__(16) uint32_t g_k_hi[SEQ * 512];               // K hi-plane [4096][512]
__device__ __align__(16) uint32_t g_v_hi[SEQ * 512];               // V hi-plane [4096][512]
__device__ __align__(16) uint32_t g_vT_hi[NH * HD * 2048];         // [h*64+d][kv-pairs]

// ---------------------------------------------------------------------------
// helpers
// ---------------------------------------------------------------------------
__device__ __forceinline__ uint2 split2(float x0, float x1) {
    uint32_t hp, lp;
    asm("cvt.rn.f16x2.f32 %0, %1, %2;" : "=r"(hp) : "f"(x1), "f"(x0));
    __half2 hb = *reinterpret_cast<__half2*>(&hp);
    float2 back = __half22float2(hb);
    float r0 = x0 - back.x;
    float r1 = x1 - back.y;
    asm("cvt.rn.f16x2.f32 %0, %1, %2;" : "=r"(lp) : "f"(r1), "f"(r0));
    return make_uint2(hp, lp);
}

__device__ __forceinline__ uint32_t pack2(float x0, float x1) {
    uint32_t hp;
    asm("cvt.rn.f16x2.f32 %0, %1, %2;" : "=r"(hp) : "f"(x1), "f"(x0));
    return hp;
}

__device__ __forceinline__ float ex2(float x) {
    float y;
    asm("ex2.approx.f32 %0, %1;" : "=f"(y) : "f"(x));
    return y;
}

// D(16x8,f32) += A(16x16,f16) * B(16x8,f16)
__device__ __forceinline__ void mma16816(float* d, const uint32_t* a,
                                         uint32_t b0, uint32_t b1) {
    asm volatile(
        "mma.sync.aligned.m16n8k16.row.col.f32.f16.f16.f32 "
        "{%0,%1,%2,%3}, {%4,%5,%6,%7}, {%8,%9}, {%0,%1,%2,%3};"
        : "+f"(d[0]), "+f"(d[1]), "+f"(d[2]), "+f"(d[3])
        : "r"(a[0]), "r"(a[1]), "r"(a[2]), "r"(a[3]), "r"(b0), "r"(b1));
}

// ---------------------------------------------------------------------------
// Prep: fp32 -> split-fp16 pairs
// ---------------------------------------------------------------------------
__global__ void split_kernel(const float4* __restrict__ src,
                             uint2* __restrict__ dst, int n4) {
    int i = blockIdx.x * blockDim.x + threadIdx.x;
    if (i >= n4) return;
    float4 v = src[i];
    dst[2 * i]     = split2(v.x, v.y);
    dst[2 * i + 1] = split2(v.z, v.w);
}

// ---------------------------------------------------------------------------
// Kernel 1: QKV GEMM, fp16x2 mma.  C[4096,3072] = A @ W^T + bias
//   Epilogue routes per region: Q -> split pairs (scaled by QSCALE),
//   K -> dense hi-plane, V -> dense hi-plane.
// ---------------------------------------------------------------------------
#define G_AS 20   // smem row stride in uint2

__global__ __launch_bounds__(256)
void qkv_gemm_mma(const float* __restrict__ bias) {
    extern __shared__ uint2 smg[];
    uint2* As = smg;                       // [2][128*G_AS]
    uint2* Bs = smg + 2 * 128 * G_AS;      // [2][128*G_AS]
    uint4* As4 = reinterpret_cast<uint4*>(As);
    uint4* Bs4 = reinterpret_cast<uint4*>(Bs);

    const int t = threadIdx.x;
    const int warp = t >> 5, lane = t & 31;
    const int g = lane >> 2, tq = lane & 3;
    const int wm = warp & 3;
    const int wn = warp >> 2;
    const int bm = blockIdx.y * 128;
    const int bn = blockIdx.x * 128;

    const uint4* A4 = reinterpret_cast<const uint4*>(g_A_split);
    const uint4* B4 = reinterpret_cast<const uint4*>(g_W_split);

    const int lr = t >> 3;
    const int lc = t & 7;

    float acc[2][8][4];
    #pragma unroll
    for (int mt = 0; mt < 2; ++mt)
        #pragma unroll
        for (int nt = 0; nt < 8; ++nt)
            #pragma unroll
            for (int j = 0; j < 4; ++j) acc[mt][nt][j] = 0.f;

    uint4 pa[4], pb[4];
    #pragma unroll
    for (int i = 0; i < 4; ++i) {
        int r = lr + i * 32;
        pa[i] = A4[(bm + r) * 256 + lc];
        pb[i] = B4[(bn + r) * 256 + lc];
    }
    #pragma unroll
    for (int i = 0; i < 4; ++i) {
        int r = lr + i * 32;
        As4[r * 10 + lc] = pa[i];
        Bs4[r * 10 + lc] = pb[i];
    }
    __syncthreads();

    for (int kt = 0; kt < 32; ++kt) {
        const int cur = kt & 1;
        if (kt < 31) {
            #pragma unroll
            for (int i = 0; i < 4; ++i) {
                int r = lr + i * 32;
                pa[i] = A4[(bm + r) * 256 + (kt + 1) * 8 + lc];
                pb[i] = B4[(bn + r) * 256 + (kt + 1) * 8 + lc];
            }
        }
        const uint2* Ab = As + cur * (128 * G_AS);
        const uint2* Bb = Bs + cur * (128 * G_AS);

        #pragma unroll
        for (int ks = 0; ks < 2; ++ks) {
            const int k2b = ks * 8;
            uint32_t ah[2][4], al[2][4];
            #pragma unroll
            for (int mt = 0; mt < 2; ++mt) {
                int row = wm * 32 + mt * 16 + g;
                uint2 f0 = Ab[row * G_AS + k2b + tq];
                uint2 f1 = Ab[(row + 8) * G_AS + k2b + tq];
                uint2 f2 = Ab[row * G_AS + k2b + tq + 4];
                uint2 f3 = Ab[(row + 8) * G_AS + k2b + tq + 4];
                ah[mt][0] = f0.x; al[mt][0] = f0.y;
                ah[mt][1] = f1.x; al[mt][1] = f1.y;
                ah[mt][2] = f2.x; al[mt][2] = f2.y;
                ah[mt][3] = f3.x; al[mt][3] = f3.y;
            }
            uint32_t bh[8][2];
            #pragma unroll
            for (int nt = 0; nt < 8; ++nt) {
                int col = wn * 64 + nt * 8 + g;
                uint2 e0 = Bb[col * G_AS + k2b + tq];
                uint2 e1 = Bb[col * G_AS + k2b + tq + 4];
                bh[nt][0] = e0.x;
                bh[nt][1] = e1.x;
            }
            #pragma unroll
            for (int mt = 0; mt < 2; ++mt)
                #pragma unroll
                for (int nt = 0; nt < 8; ++nt) {
                    mma16816(acc[mt][nt], ah[mt], bh[nt][0], bh[nt][1]);
                    mma16816(acc[mt][nt], al[mt], bh[nt][0], bh[nt][1]);
                }
        }
        if (kt < 31) {
            uint4* Ad = As4 + (cur ^ 1) * (128 * G_AS / 2);
            uint4* Bd = Bs4 + (cur ^ 1) * (128 * G_AS / 2);
            #pragma unroll
            for (int i = 0; i < 4; ++i) {
                int r = lr + i * 32;
                Ad[r * 10 + lc] = pa[i];
                Bd[r * 10 + lc] = pb[i];
            }
        }
        __syncthreads();
    }

    // epilogue: + bias; route per region
    const int region = bn >> 10;         // 0=Q, 1=K, 2=V (bn multiple of 128)
    const float scale = (region == 0) ? QSCALE : 1.0f;
    #pragma unroll
    for (int mt = 0; mt < 2; ++mt) {
        int r0 = bm + wm * 32 + mt * 16 + g;
        #pragma unroll
        for (int nt = 0; nt < 8; ++nt) {
            int col0 = bn + wn * 64 + nt * 8 + 2 * tq;
            float b0 = bias[col0], b1 = bias[col0 + 1];
            float v00 = (acc[mt][nt][0] + b0) * scale;
            float v01 = (acc[mt][nt][1] + b1) * scale;
            float v10 = (acc[mt][nt][2] + b0) * scale;
            float v11 = (acc[mt][nt][3] + b1) * scale;
            if (region == 0) {
                g_qkv_split[r0 * QKV_C2 + (col0 >> 1)]       = split2(v00, v01);
                g_qkv_split[(r0 + 8) * QKV_C2 + (col0 >> 1)] = split2(v10, v11);
            } else if (region == 1) {
                int c = (col0 - EMB) >> 1;
                g_k_hi[r0 * 512 + c]       = pack2(v00, v01);
                g_k_hi[(r0 + 8) * 512 + c] = pack2(v10, v11);
            } else {
                int c = (col0 - 2 * EMB) >> 1;
                g_v_hi[r0 * 512 + c]       = pack2(v00, v01);
                g_v_hi[(r0 + 8) * 512 + c] = pack2(v10, v11);
            }
        }
    }
}

// ---------------------------------------------------------------------------
// Kernel 2: V transpose  g_v_hi -> g_vT_hi[h][d][kv-pair]
// ---------------------------------------------------------------------------
__global__ void vT_kernel() {
    int i = blockIdx.x * 256 + threadIdx.x;       // 16*64*2048 total
    int m2 = i & 2047;
    int d  = (i >> 11) & 63;
    int h  = i >> 17;
    int col = h * 32 + (d >> 1);
    uint32_t p0 = g_v_hi[(2 * m2) * 512 + col];
    uint32_t p1 = g_v_hi[(2 * m2 + 1) * 512 + col];
    uint32_t sh = (d & 1) * 16;
    g_vT_hi[((h * 64 + d) << 11) + m2] =
        ((p0 >> sh) & 0xffffu) | (((p1 >> sh) & 0xffffu) << 16);
}

// ---------------------------------------------------------------------------
// Kernel 3: flash attention, fp16 mma, PV pipelined one tile behind S.
//   Per iter: prefetch LDG(t+1); S(t) mma; PV(t-1) mma; softmax(t)
//   (overlaps PV drain; o-scale last); smem stores; one barrier.
//   K double-buffered, V triple-buffered (hi-plane only).
// ---------------------------------------------------------------------------
#define KST 36          // K/V smem row stride in uint32 (144B)
#define QST 36          // Q smem row stride in uint2 (288B)
#define KBUF (64 * KST) // 2304 uint32 per K/V buffer
#define SM_K_OFF (128 * QST * 2)         // uint32 offset of K (Q = 9216 u32)
#define SM_V_OFF (SM_K_OFF + 2 * KBUF)
#define ATTN_SMEM ((SM_V_OFF + 3 * KBUF) * 4)   // 82944 bytes
#define NT (SEQ / 64)

__global__ __launch_bounds__(256)
void attn_mma(const float* __restrict__ trace, float* __restrict__ out) {
    extern __shared__ uint32_t smw[];
    uint2*    Qs  = reinterpret_cast<uint2*>(smw);
    uint32_t* Ks  = smw + SM_K_OFF;
    uint32_t* Vs  = smw + SM_V_OFF;
    uint4*    Qs4 = reinterpret_cast<uint4*>(Qs);

    const int t = threadIdx.x;
    const int warp = t >> 5, lane = t & 31;
    const int g = lane >> 2, tq = lane & 3;
    const int h = blockIdx.y;
    const int q0 = blockIdx.x * 128;

    const uint4* G4  = reinterpret_cast<const uint4*>(g_qkv_split); // row = 768 u4
    const uint4* KH4 = reinterpret_cast<const uint4*>(g_k_hi);      // row = 128 u4
    const uint4* VT4 = reinterpret_cast<const uint4*>(g_vT_hi);     // row = 512 u4

    // ---- load Q tile to smem (hi+lo pairs) ----
    {
        const int lr = t >> 4, lc = t & 15;
        #pragma unroll
        for (int i = 0; i < 8; ++i) {
            int r = lr + i * 16;
            Qs4[r * (QST / 2) + lc] = G4[(q0 + r) * 768 + h * 16 + lc];
        }
    }

    // K/V loader mapping: f = t, t+256 -> row f>>3 (0..63), uint4 col f&7
    const int kr = t >> 3;        // 0..31 (+32)
    const int kc = t & 7;

    // ---- preload KV tile 0 ----
    uint4 pk[2], pv[2];
    #pragma unroll
    for (int i = 0; i < 2; ++i) {
        int r = kr + i * 32;
        pk[i] = KH4[r * 128 + h * 8 + kc];
        pv[i] = VT4[(h * 64 + r) * 512 + kc];
    }
    #pragma unroll
    for (int i = 0; i < 2; ++i) {
        int r = kr + i * 32;
        *reinterpret_cast<uint4*>(&Ks[r * KST + 4 * kc]) = pk[i];
        *reinterpret_cast<uint4*>(&Vs[r * KST + 4 * kc]) = pv[i];
    }
    __syncthreads();

    // ---- Q fragments -> registers ----
    const int qr = warp * 16;
    uint32_t qh[4][4], ql[4][4];
    #pragma unroll
    for (int ks = 0; ks < 4; ++ks) {
        uint2 f0 = Qs[(qr + g) * QST + 8 * ks + tq];
        uint2 f1 = Qs[(qr + g + 8) * QST + 8 * ks + tq];
        uint2 f2 = Qs[(qr + g) * QST + 8 * ks + tq + 4];
        uint2 f3 = Qs[(qr + g + 8) * QST + 8 * ks + tq + 4];
        qh[ks][0] = f0.x; ql[ks][0] = f0.y;
        qh[ks][1] = f1.x; ql[ks][1] = f1.y;
        qh[ks][2] = f2.x; ql[ks][2] = f2.y;
        qh[ks][3] = f3.x; ql[ks][3] = f3.y;
    }

    float m0 = -1e30f, m1 = -1e30f, l0 = 0.f, l1 = 0.f;
    float o[8][4];
    #pragma unroll
    for (int nt = 0; nt < 8; ++nt)
        #pragma unroll
        for (int j = 0; j < 4; ++j) o[nt][j] = 0.f;

    uint32_t ph[4][4];   // quantized P of the PREVIOUS tile

    for (int it = 0; it < NT; ++it) {
        // ---- prefetch next KV tile (gmem -> regs) ----
        if (it < NT - 1) {
            int kv0 = (it + 1) * 64;
            #pragma unroll
            for (int i = 0; i < 2; ++i) {
                int r = kr + i * 32;
                pk[i] = KH4[(kv0 + r) * 128 + h * 8 + kc];
                pv[i] = VT4[(h * 64 + r) * 512 + (it + 1) * 8 + kc];
            }
        }

        // ---- S(t) = Q @ K_hi^T  (2-pass: q_hi + q_lo) ----
        const uint32_t* Kb = Ks + (it & 1) * KBUF;
        float s[8][4];
        #pragma unroll
        for (int nt = 0; nt < 8; ++nt)
            #pragma unroll
            for (int j = 0; j < 4; ++j) s[nt][j] = 0.f;

        #pragma unroll
        for (int ks = 0; ks < 4; ++ks) {
            #pragma unroll
            for (int nt = 0; nt < 8; ++nt) {
                int n = nt * 8 + g;
                uint32_t e0 = Kb[n * KST + 8 * ks + tq];
                uint32_t e1 = Kb[n * KST + 8 * ks + tq + 4];
                mma16816(s[nt], qh[ks], e0, e1);
                mma16816(s[nt], ql[ks], e0, e1);
            }
        }

        // ---- PV(t-1): O += P_prev @ V_prev  (drains under softmax below) ----
        if (it > 0) {
            const uint32_t* Vb = Vs + ((it - 1) % 3) * KBUF;
            #pragma unroll
            for (int ks = 0; ks < 4; ++ks) {
                #pragma unroll
                for (int nt = 0; nt < 8; ++nt) {
                    int n = nt * 8 + g;
                    uint32_t e0 = Vb[n * KST + 8 * ks + tq];
                    uint32_t e1 = Vb[n * KST + 8 * ks + tq + 4];
                    mma16816(o[nt], ph[ks], e0, e1);
                }
            }
        }

        // ---- softmax(t): max, exp2, pack, l  (independent of o) ----
        float rm0 = -1e30f, rm1 = -1e30f;
        #pragma unroll
        for (int nt = 0; nt < 8; ++nt) {
            rm0 = fmaxf(rm0, fmaxf(s[nt][0], s[nt][1]));
            rm1 = fmaxf(rm1, fmaxf(s[nt][2], s[nt][3]));
        }
        #pragma unroll
        for (int w = 1; w < 4; w <<= 1) {
            rm0 = fmaxf(rm0, __shfl_xor_sync(0xffffffffu, rm0, w));
            rm1 = fmaxf(rm1, __shfl_xor_sync(0xffffffffu, rm1, w));
        }
        float n0 = fmaxf(m0, rm0), n1 = fmaxf(m1, rm1);
        float a0 = ex2(m0 - n0), a1 = ex2(m1 - n1);
        m0 = n0; m1 = n1;

        float rs0 = 0.f, rs1 = 0.f;
        #pragma unroll
        for (int ks = 0; ks < 4; ++ks) {
            float p00 = ex2(s[2 * ks][0] - n0);
            float p01 = ex2(s[2 * ks][1] - n0);
            float p02 = ex2(s[2 * ks][2] - n1);
            float p03 = ex2(s[2 * ks][3] - n1);
            float p10 = ex2(s[2 * ks + 1][0] - n0);
            float p11 = ex2(s[2 * ks + 1][1] - n0);
            float p12 = ex2(s[2 * ks + 1][2] - n1);
            float p13 = ex2(s[2 * ks + 1][3] - n1);
            ph[ks][0] = pack2(p00, p01);
            ph[ks][1] = pack2(p02, p03);
            ph[ks][2] = pack2(p10, p11);
            ph[ks][3] = pack2(p12, p13);
            float2 q00 = __half22float2(*reinterpret_cast<__half2*>(&ph[ks][0]));
            float2 q01 = __half22float2(*reinterpret_cast<__half2*>(&ph[ks][1]));
            float2 q10 = __half22float2(*reinterpret_cast<__half2*>(&ph[ks][2]));
            float2 q11 = __half22float2(*reinterpret_cast<__half2*>(&ph[ks][3]));
            rs0 += (q00.x + q00.y) + (q10.x + q10.y);
            rs1 += (q01.x + q01.y) + (q11.x + q11.y);
        }
        #pragma unroll
        for (int w = 1; w < 4; w <<= 1) {
            rs0 += __shfl_xor_sync(0xffffffffu, rs0, w);
            rs1 += __shfl_xor_sync(0xffffffffu, rs1, w);
        }
        l0 = l0 * a0 + rs0;
        l1 = l1 * a1 + rs1;

        // o-scale: needs PV(t-1) results — placed last for overlap
        #pragma unroll
        for (int nt = 0; nt < 8; ++nt) {
            o[nt][0] *= a0; o[nt][1] *= a0;
            o[nt][2] *= a1; o[nt][3] *= a1;
        }

        // ---- store prefetched tile (t+1): K buf (t+1)&1, V buf (t+1)%3 ----
        if (it < NT - 1) {
            uint32_t* Kd = Ks + ((it + 1) & 1) * KBUF;
            uint32_t* Vd = Vs + ((it + 1) % 3) * KBUF;
            #pragma unroll
            for (int i = 0; i < 2; ++i) {
                int r = kr + i * 32;
                *reinterpret_cast<uint4*>(&Kd[r * KST + 4 * kc]) = pk[i];
                *reinterpret_cast<uint4*>(&Vd[r * KST + 4 * kc]) = pv[i];
            }
        }
        __syncthreads();
    }

    // ---- final PV for the last tile ----
    {
        const uint32_t* Vb = Vs + ((NT - 1) % 3) * KBUF;
        #pragma unroll
        for (int ks = 0; ks < 4; ++ks) {
            #pragma unroll
            for (int nt = 0; nt < 8; ++nt) {
                int n = nt * 8 + g;
                uint32_t e0 = Vb[n * KST + 8 * ks + tq];
                uint32_t e1 = Vb[n * KST + 8 * ks + tq + 4];
                mma16816(o[nt], ph[ks], e0, e1);
            }
        }
    }

    // ---- epilogue: 1/l, Hebbian diag, store ----
    float inv0 = 1.f / l0, inv1 = 1.f / l1;
    int row0 = q0 + qr + g, row1 = row0 + 8;
    #pragma unroll
    for (int nt = 0; nt < 8; ++nt) {
        int d0 = nt * 8 + 2 * tq;
        float dd0 = trace[h * 4096 + d0 * 65];
        float dd1 = trace[h * 4096 + (d0 + 1) * 65];
        float2 r0 = make_float2(o[nt][0] * inv0 * dd0, o[nt][1] * inv0 * dd1);
        float2 r1 = make_float2(o[nt][2] * inv1 * dd0, o[nt][3] * inv1 * dd1);
        *(float2*)&out[row0 * EMB + h * HD + d0] = r0;
        *(float2*)&out[row1 * EMB + h * HD + d0] = r1;
    }
}

// ---------------------------------------------------------------------------
extern "C" void kernel_launch(void* const* d_in, const int* in_sizes, int n_in,
                              void* d_out, int out_size) {
    (void)in_sizes; (void)n_in; (void)out_size;
    const float* hidden = (const float*)d_in[0];   // [1,4096,1024]
    const float* W      = (const float*)d_in[1];   // [3072,1024]
    const float* bias   = (const float*)d_in[2];   // [3072]
    const float* trace  = (const float*)d_in[3];   // [16,64,64]
    float* out = (float*)d_out;                    // [1,4096,1024]

    uint2* dA; cudaGetSymbolAddress((void**)&dA, g_A_split);
    uint2* dW; cudaGetSymbolAddress((void**)&dW, g_W_split);

    // prep: split inputs
    {
        int n4a = SEQ * EMB / 4;
        split_kernel<<<(n4a + 255) / 256, 256>>>((const float4*)hidden, dA, n4a);
        int n4w = QKV_COLS * EMB / 4;
        split_kernel<<<(n4w + 255) / 256, 256>>>((const float4*)W, dW, n4w);
    }

    static int inited = 0;
    if (!inited) {
        cudaFuncSetAttribute(qkv_gemm_mma,
                             cudaFuncAttributeMaxDynamicSharedMemorySize, 81920);
        cudaFuncSetAttribute(attn_mma,
                             cudaFuncAttributeMaxDynamicSharedMemorySize, ATTN_SMEM);
        inited = 1;
    }

    qkv_gemm_mma<<<dim3(QKV_COLS / 128, SEQ / 128), 256, 81920>>>(bias);
    vT_kernel<<<(NH * HD * 2048) / 256, 256>>>();
    attn_mma<<<dim3(SEQ / 128, NH), 256, ATTN_SMEM>>>(trace, out);
}

// round 15
// speedup vs baseline: 5.0958x; 1.1056x over previous
#include <cuda_runtime.h>
#include <cuda_fp16.h>
#include <stdint.h>

#define SEQ 4096
#define EMB 1024
#define NH 16
#define HD 64
#define QKV_COLS 3072

// Q pre-scale: 1/sqrt(64) * log2(e)  (softmax runs in exp2 domain)
#define QSCALE 0.1803368801111204f

// ---- static device scratch (no runtime allocation) ----
__device__ __align__(16) uint2    g_A_split[SEQ * (EMB / 2)];      // [4096][512]
__device__ __align__(16) uint2    g_W_split[QKV_COLS * (EMB / 2)]; // [3072][512]
__device__ __align__(16) uint32_t g_q_hi[SEQ * 512];               // Q hi-plane
__device__ __align__(16) uint32_t g_k_hi[SEQ * 512];               // K hi-plane
__device__ __align__(16) uint32_t g_v_hi[SEQ * 512];               // V hi-plane
__device__ __align__(16) uint32_t g_vT_hi[NH * HD * 2048];         // [h*64+d][kv-pairs]

// ---------------------------------------------------------------------------
// helpers
// ---------------------------------------------------------------------------
__device__ __forceinline__ uint2 split2(float x0, float x1) {
    uint32_t hp, lp;
    asm("cvt.rn.f16x2.f32 %0, %1, %2;" : "=r"(hp) : "f"(x1), "f"(x0));
    __half2 hb = *reinterpret_cast<__half2*>(&hp);
    float2 back = __half22float2(hb);
    float r0 = x0 - back.x;
    float r1 = x1 - back.y;
    asm("cvt.rn.f16x2.f32 %0, %1, %2;" : "=r"(lp) : "f"(r1), "f"(r0));
    return make_uint2(hp, lp);
}

__device__ __forceinline__ uint32_t pack2(float x0, float x1) {
    uint32_t hp;
    asm("cvt.rn.f16x2.f32 %0, %1, %2;" : "=r"(hp) : "f"(x1), "f"(x0));
    return hp;
}

__device__ __forceinline__ float ex2(float x) {
    float y;
    asm("ex2.approx.f32 %0, %1;" : "=f"(y) : "f"(x));
    return y;
}

// D(16x8,f32) += A(16x16,f16) * B(16x8,f16)
__device__ __forceinline__ void mma16816(float* d, const uint32_t* a,
                                         uint32_t b0, uint32_t b1) {
    asm volatile(
        "mma.sync.aligned.m16n8k16.row.col.f32.f16.f16.f32 "
        "{%0,%1,%2,%3}, {%4,%5,%6,%7}, {%8,%9}, {%0,%1,%2,%3};"
        : "+f"(d[0]), "+f"(d[1]), "+f"(d[2]), "+f"(d[3])
        : "r"(a[0]), "r"(a[1]), "r"(a[2]), "r"(a[3]), "r"(b0), "r"(b1));
}

// ---------------------------------------------------------------------------
// Prep: fp32 -> split-fp16 pairs
// ---------------------------------------------------------------------------
__global__ void split_kernel(const float4* __restrict__ src,
                             uint2* __restrict__ dst, int n4) {
    int i = blockIdx.x * blockDim.x + threadIdx.x;
    if (i >= n4) return;
    float4 v = src[i];
    dst[2 * i]     = split2(v.x, v.y);
    dst[2 * i + 1] = split2(v.z, v.w);
}

// ---------------------------------------------------------------------------
// Kernel 1: QKV GEMM, fp16x2 mma.  C[4096,3072] = A @ W^T + bias
//   Epilogue: all regions -> dense fp16 hi-planes (Q scaled by QSCALE).
// ---------------------------------------------------------------------------
#define G_AS 20   // smem row stride in uint2

__global__ __launch_bounds__(256)
void qkv_gemm_mma(const float* __restrict__ bias) {
    extern __shared__ uint2 smg[];
    uint2* As = smg;                       // [2][128*G_AS]
    uint2* Bs = smg + 2 * 128 * G_AS;      // [2][128*G_AS]
    uint4* As4 = reinterpret_cast<uint4*>(As);
    uint4* Bs4 = reinterpret_cast<uint4*>(Bs);

    const int t = threadIdx.x;
    const int warp = t >> 5, lane = t & 31;
    const int g = lane >> 2, tq = lane & 3;
    const int wm = warp & 3;
    const int wn = warp >> 2;
    const int bm = blockIdx.y * 128;
    const int bn = blockIdx.x * 128;

    const uint4* A4 = reinterpret_cast<const uint4*>(g_A_split);
    const uint4* B4 = reinterpret_cast<const uint4*>(g_W_split);

    const int lr = t >> 3;
    const int lc = t & 7;

    float acc[2][8][4];
    #pragma unroll
    for (int mt = 0; mt < 2; ++mt)
        #pragma unroll
        for (int nt = 0; nt < 8; ++nt)
            #pragma unroll
            for (int j = 0; j < 4; ++j) acc[mt][nt][j] = 0.f;

    uint4 pa[4], pb[4];
    #pragma unroll
    for (int i = 0; i < 4; ++i) {
        int r = lr + i * 32;
        pa[i] = A4[(bm + r) * 256 + lc];
        pb[i] = B4[(bn + r) * 256 + lc];
    }
    #pragma unroll
    for (int i = 0; i < 4; ++i) {
        int r = lr + i * 32;
        As4[r * 10 + lc] = pa[i];
        Bs4[r * 10 + lc] = pb[i];
    }
    __syncthreads();

    for (int kt = 0; kt < 32; ++kt) {
        const int cur = kt & 1;
        if (kt < 31) {
            #pragma unroll
            for (int i = 0; i < 4; ++i) {
                int r = lr + i * 32;
                pa[i] = A4[(bm + r) * 256 + (kt + 1) * 8 + lc];
                pb[i] = B4[(bn + r) * 256 + (kt + 1) * 8 + lc];
            }
        }
        const uint2* Ab = As + cur * (128 * G_AS);
        const uint2* Bb = Bs + cur * (128 * G_AS);

        #pragma unroll
        for (int ks = 0; ks < 2; ++ks) {
            const int k2b = ks * 8;
            uint32_t ah[2][4], al[2][4];
            #pragma unroll
            for (int mt = 0; mt < 2; ++mt) {
                int row = wm * 32 + mt * 16 + g;
                uint2 f0 = Ab[row * G_AS + k2b + tq];
                uint2 f1 = Ab[(row + 8) * G_AS + k2b + tq];
                uint2 f2 = Ab[row * G_AS + k2b + tq + 4];
                uint2 f3 = Ab[(row + 8) * G_AS + k2b + tq + 4];
                ah[mt][0] = f0.x; al[mt][0] = f0.y;
                ah[mt][1] = f1.x; al[mt][1] = f1.y;
                ah[mt][2] = f2.x; al[mt][2] = f2.y;
                ah[mt][3] = f3.x; al[mt][3] = f3.y;
            }
            uint32_t bh[8][2];
            #pragma unroll
            for (int nt = 0; nt < 8; ++nt) {
                int col = wn * 64 + nt * 8 + g;
                uint2 e0 = Bb[col * G_AS + k2b + tq];
                uint2 e1 = Bb[col * G_AS + k2b + tq + 4];
                bh[nt][0] = e0.x;
                bh[nt][1] = e1.x;
            }
            #pragma unroll
            for (int mt = 0; mt < 2; ++mt)
                #pragma unroll
                for (int nt = 0; nt < 8; ++nt) {
                    mma16816(acc[mt][nt], ah[mt], bh[nt][0], bh[nt][1]);
                    mma16816(acc[mt][nt], al[mt], bh[nt][0], bh[nt][1]);
                }
        }
        if (kt < 31) {
            uint4* Ad = As4 + (cur ^ 1) * (128 * G_AS / 2);
            uint4* Bd = Bs4 + (cur ^ 1) * (128 * G_AS / 2);
            #pragma unroll
            for (int i = 0; i < 4; ++i) {
                int r = lr + i * 32;
                Ad[r * 10 + lc] = pa[i];
                Bd[r * 10 + lc] = pb[i];
            }
        }
        __syncthreads();
    }

    // epilogue: + bias; all regions -> dense hi-planes
    const int region = bn >> 10;         // 0=Q, 1=K, 2=V
    const float scale = (region == 0) ? QSCALE : 1.0f;
    uint32_t* dst = (region == 0) ? g_q_hi : (region == 1) ? g_k_hi : g_v_hi;
    const int cbase = bn - (region << 10);
    #pragma unroll
    for (int mt = 0; mt < 2; ++mt) {
        int r0 = bm + wm * 32 + mt * 16 + g;
        #pragma unroll
        for (int nt = 0; nt < 8; ++nt) {
            int col0 = cbase + wn * 64 + nt * 8 + 2 * tq;
            float b0 = bias[(region << 10) + col0];
            float b1 = bias[(region << 10) + col0 + 1];
            float v00 = (acc[mt][nt][0] + b0) * scale;
            float v01 = (acc[mt][nt][1] + b1) * scale;
            float v10 = (acc[mt][nt][2] + b0) * scale;
            float v11 = (acc[mt][nt][3] + b1) * scale;
            int c = col0 >> 1;
            dst[r0 * 512 + c]       = pack2(v00, v01);
            dst[(r0 + 8) * 512 + c] = pack2(v10, v11);
        }
    }
}

// ---------------------------------------------------------------------------
// Kernel 2: V transpose  g_v_hi -> g_vT_hi[h][d][kv-pair]
// ---------------------------------------------------------------------------
__global__ void vT_kernel() {
    int i = blockIdx.x * 256 + threadIdx.x;       // 16*64*2048 total
    int m2 = i & 2047;
    int d  = (i >> 11) & 63;
    int h  = i >> 17;
    int col = h * 32 + (d >> 1);
    uint32_t p0 = g_v_hi[(2 * m2) * 512 + col];
    uint32_t p1 = g_v_hi[(2 * m2 + 1) * 512 + col];
    uint32_t sh = (d & 1) * 16;
    g_vT_hi[((h * 64 + d) << 11) + m2] =
        ((p0 >> sh) & 0xffffu) | (((p1 >> sh) & 0xffffu) << 16);
}

// ---------------------------------------------------------------------------
// Kernel 3: flash attention, fp16 mma, hi-planes only (1-pass S, 1-pass PV).
//   Per iter: prefetch LDG(t+1); S(t) mma; PV(t-1) mma; softmax(t); stores.
//   K double-buffered, V triple-buffered. Consistent quantized normalizer.
// ---------------------------------------------------------------------------
#define KST 36          // K/V/Q smem row stride in uint32 (144B)
#define KBUF (64 * KST)
#define SM_K_OFF (128 * KST)             // Q = 128 rows x KST u32 = 4608 u32
#define SM_V_OFF (SM_K_OFF + 2 * KBUF)
#define ATTN_SMEM ((SM_V_OFF + 3 * KBUF) * 4)   // 64512 bytes -> 3 CTAs/SM
#define NT (SEQ / 64)

__global__ __launch_bounds__(256)
void attn_mma(const float* __restrict__ trace, float* __restrict__ out) {
    extern __shared__ uint32_t smw[];
    uint32_t* Qs  = smw;
    uint32_t* Ks  = smw + SM_K_OFF;
    uint32_t* Vs  = smw + SM_V_OFF;
    uint4*    Qs4 = reinterpret_cast<uint4*>(Qs);

    const int t = threadIdx.x;
    const int warp = t >> 5, lane = t & 31;
    const int g = lane >> 2, tq = lane & 3;
    const int h = blockIdx.y;
    const int q0 = blockIdx.x * 128;

    const uint4* QH4 = reinterpret_cast<const uint4*>(g_q_hi);      // row = 128 u4
    const uint4* KH4 = reinterpret_cast<const uint4*>(g_k_hi);      // row = 128 u4
    const uint4* VT4 = reinterpret_cast<const uint4*>(g_vT_hi);     // row = 512 u4

    // ---- load Q tile to smem (hi-plane, 128 rows x 8 uint4) ----
    #pragma unroll
    for (int j = 0; j < 4; ++j) {
        int f = t + 256 * j;
        int r = f >> 3, c = f & 7;
        Qs4[r * (KST / 4) + c] = QH4[(q0 + r) * 128 + h * 8 + c];
    }

    // K/V loader mapping: rows kr, kr+32; uint4 col kc
    const int kr = t >> 3;        // 0..31
    const int kc = t & 7;

    // ---- preload KV tile 0 ----
    uint4 pk[2], pv[2];
    #pragma unroll
    for (int i = 0; i < 2; ++i) {
        int r = kr + i * 32;
        pk[i] = KH4[r * 128 + h * 8 + kc];
        pv[i] = VT4[(h * 64 + r) * 512 + kc];
    }
    #pragma unroll
    for (int i = 0; i < 2; ++i) {
        int r = kr + i * 32;
        *reinterpret_cast<uint4*>(&Ks[r * KST + 4 * kc]) = pk[i];
        *reinterpret_cast<uint4*>(&Vs[r * KST + 4 * kc]) = pv[i];
    }
    __syncthreads();

    // ---- Q fragments -> registers (hi only) ----
    const int qr = warp * 16;
    uint32_t qh[4][4];
    #pragma unroll
    for (int ks = 0; ks < 4; ++ks) {
        qh[ks][0] = Qs[(qr + g) * KST + 8 * ks + tq];
        qh[ks][1] = Qs[(qr + g + 8) * KST + 8 * ks + tq];
        qh[ks][2] = Qs[(qr + g) * KST + 8 * ks + tq + 4];
        qh[ks][3] = Qs[(qr + g + 8) * KST + 8 * ks + tq + 4];
    }

    float m0 = -1e30f, m1 = -1e30f, l0 = 0.f, l1 = 0.f;
    float o[8][4];
    #pragma unroll
    for (int nt = 0; nt < 8; ++nt)
        #pragma unroll
        for (int j = 0; j < 4; ++j) o[nt][j] = 0.f;

    uint32_t ph[4][4];   // quantized P of the PREVIOUS tile

    for (int it = 0; it < NT; ++it) {
        // ---- prefetch next KV tile (gmem -> regs) ----
        if (it < NT - 1) {
            int kv0 = (it + 1) * 64;
            #pragma unroll
            for (int i = 0; i < 2; ++i) {
                int r = kr + i * 32;
                pk[i] = KH4[(kv0 + r) * 128 + h * 8 + kc];
                pv[i] = VT4[(h * 64 + r) * 512 + (it + 1) * 8 + kc];
            }
        }

        // ---- S(t) = Q_hi @ K_hi^T  (single pass) ----
        const uint32_t* Kb = Ks + (it & 1) * KBUF;
        float s[8][4];
        #pragma unroll
        for (int nt = 0; nt < 8; ++nt)
            #pragma unroll
            for (int j = 0; j < 4; ++j) s[nt][j] = 0.f;

        #pragma unroll
        for (int ks = 0; ks < 4; ++ks) {
            #pragma unroll
            for (int nt = 0; nt < 8; ++nt) {
                int n = nt * 8 + g;
                uint32_t e0 = Kb[n * KST + 8 * ks + tq];
                uint32_t e1 = Kb[n * KST + 8 * ks + tq + 4];
                mma16816(s[nt], qh[ks], e0, e1);
            }
        }

        // ---- PV(t-1): O += P_prev @ V_prev  (drains under softmax) ----
        if (it > 0) {
            const uint32_t* Vb = Vs + ((it - 1) % 3) * KBUF;
            #pragma unroll
            for (int ks = 0; ks < 4; ++ks) {
                #pragma unroll
                for (int nt = 0; nt < 8; ++nt) {
                    int n = nt * 8 + g;
                    uint32_t e0 = Vb[n * KST + 8 * ks + tq];
                    uint32_t e1 = Vb[n * KST + 8 * ks + tq + 4];
                    mma16816(o[nt], ph[ks], e0, e1);
                }
            }
        }

        // ---- softmax(t): max, exp2, pack, l  (independent of o) ----
        float rm0 = -1e30f, rm1 = -1e30f;
        #pragma unroll
        for (int nt = 0; nt < 8; ++nt) {
            rm0 = fmaxf(rm0, fmaxf(s[nt][0], s[nt][1]));
            rm1 = fmaxf(rm1, fmaxf(s[nt][2], s[nt][3]));
        }
        #pragma unroll
        for (int w = 1; w < 4; w <<= 1) {
            rm0 = fmaxf(rm0, __shfl_xor_sync(0xffffffffu, rm0, w));
            rm1 = fmaxf(rm1, __shfl_xor_sync(0xffffffffu, rm1, w));
        }
        float n0 = fmaxf(m0, rm0), n1 = fmaxf(m1, rm1);
        float a0 = ex2(m0 - n0), a1 = ex2(m1 - n1);
        m0 = n0; m1 = n1;

        float rs0 = 0.f, rs1 = 0.f;
        #pragma unroll
        for (int ks = 0; ks < 4; ++ks) {
            float p00 = ex2(s[2 * ks][0] - n0);
            float p01 = ex2(s[2 * ks][1] - n0);
            float p02 = ex2(s[2 * ks][2] - n1);
            float p03 = ex2(s[2 * ks][3] - n1);
            float p10 = ex2(s[2 * ks + 1][0] - n0);
            float p11 = ex2(s[2 * ks + 1][1] - n0);
            float p12 = ex2(s[2 * ks + 1][2] - n1);
            float p13 = ex2(s[2 * ks + 1][3] - n1);
            ph[ks][0] = pack2(p00, p01);
            ph[ks][1] = pack2(p02, p03);
            ph[ks][2] = pack2(p10, p11);
            ph[ks][3] = pack2(p12, p13);
            float2 q00 = __half22float2(*reinterpret_cast<__half2*>(&ph[ks][0]));
            float2 q01 = __half22float2(*reinterpret_cast<__half2*>(&ph[ks][1]));
            float2 q10 = __half22float2(*reinterpret_cast<__half2*>(&ph[ks][2]));
            float2 q11 = __half22float2(*reinterpret_cast<__half2*>(&ph[ks][3]));
            rs0 += (q00.x + q00.y) + (q10.x + q10.y);
            rs1 += (q01.x + q01.y) + (q11.x + q11.y);
        }
        #pragma unroll
        for (int w = 1; w < 4; w <<= 1) {
            rs0 += __shfl_xor_sync(0xffffffffu, rs0, w);
            rs1 += __shfl_xor_sync(0xffffffffu, rs1, w);
        }
        l0 = l0 * a0 + rs0;
        l1 = l1 * a1 + rs1;

        // o-scale last (needs PV(t-1) results -> overlap)
        #pragma unroll
        for (int nt = 0; nt < 8; ++nt) {
            o[nt][0] *= a0; o[nt][1] *= a0;
            o[nt][2] *= a1; o[nt][3] *= a1;
        }

        // ---- store prefetched tile (t+1) ----
        if (it < NT - 1) {
            uint32_t* Kd = Ks + ((it + 1) & 1) * KBUF;
            uint32_t* Vd = Vs + ((it + 1) % 3) * KBUF;
            #pragma unroll
            for (int i = 0; i < 2; ++i) {
                int r = kr + i * 32;
                *reinterpret_cast<uint4*>(&Kd[r * KST + 4 * kc]) = pk[i];
                *reinterpret_cast<uint4*>(&Vd[r * KST + 4 * kc]) = pv[i];
            }
        }
        __syncthreads();
    }

    // ---- final PV for the last tile ----
    {
        const uint32_t* Vb = Vs + ((NT - 1) % 3) * KBUF;
        #pragma unroll
        for (int ks = 0; ks < 4; ++ks) {
            #pragma unroll
            for (int nt = 0; nt < 8; ++nt) {
                int n = nt * 8 + g;
                uint32_t e0 = Vb[n * KST + 8 * ks + tq];
                uint32_t e1 = Vb[n * KST + 8 * ks + tq + 4];
                mma16816(o[nt], ph[ks], e0, e1);
            }
        }
    }

    // ---- epilogue: 1/l, Hebbian diag, store ----
    float inv0 = 1.f / l0, inv1 = 1.f / l1;
    int row0 = q0 + qr + g, row1 = row0 + 8;
    #pragma unroll
    for (int nt = 0; nt < 8; ++nt) {
        int d0 = nt * 8 + 2 * tq;
        float dd0 = trace[h * 4096 + d0 * 65];
        float dd1 = trace[h * 4096 + (d0 + 1) * 65];
        float2 r0 = make_float2(o[nt][0] * inv0 * dd0, o[nt][1] * inv0 * dd1);
        float2 r1 = make_float2(o[nt][2] * inv1 * dd0, o[nt][3] * inv1 * dd1);
        *(float2*)&out[row0 * EMB + h * HD + d0] = r0;
        *(float2*)&out[row1 * EMB + h * HD + d0] = r1;
    }
}

// ---------------------------------------------------------------------------
extern "C" void kernel_launch(void* const* d_in, const int* in_sizes, int n_in,
                              void* d_out, int out_size) {
    (void)in_sizes; (void)n_in; (void)out_size;
    const float* hidden = (const float*)d_in[0];   // [1,4096,1024]
    const float* W      = (const float*)d_in[1];   // [3072,1024]
    const float* bias   = (const float*)d_in[2];   // [3072]
    const float* trace  = (const float*)d_in[3];   // [16,64,64]
    float* out = (float*)d_out;                    // [1,4096,1024]

    uint2* dA; cudaGetSymbolAddress((void**)&dA, g_A_split);
    uint2* dW; cudaGetSymbolAddress((void**)&dW, g_W_split);

    // prep: split inputs
    {
        int n4a = SEQ * EMB / 4;
        split_kernel<<<(n4a + 255) / 256, 256>>>((const float4*)hidden, dA, n4a);
        int n4w = QKV_COLS * EMB / 4;
        split_kernel<<<(n4w + 255) / 256, 256>>>((const float4*)W, dW, n4w);
    }

    static int inited = 0;
    if (!inited) {
        cudaFuncSetAttribute(qkv_gemm_mma,
                             cudaFuncAttributeMaxDynamicSharedMemorySize, 81920);
        cudaFuncSetAttribute(attn_mma,
                             cudaFuncAttributeMaxDynamicSharedMemorySize, ATTN_SMEM);
        inited = 1;
    }

    qkv_gemm_mma<<<dim3(QKV_COLS / 128, SEQ / 128), 256, 81920>>>(bias);
    vT_kernel<<<(NH * HD * 2048) / 256, 256>>>();
    attn_mma<<<dim3(SEQ / 128, NH), 256, ATTN_SMEM>>>(trace, out);
}

// round 16
// speedup vs baseline: 6.1279x; 1.2025x over previous
#include <cuda_runtime.h>
#include <cuda_fp16.h>
#include <stdint.h>

#define SEQ 4096
#define EMB 1024
#define NH 16
#define HD 64
#define QKV_COLS 3072

// Q pre-scale: 1/sqrt(64) * log2(e)  (softmax runs in exp2 domain)
#define QSCALE 0.1803368801111204f

// ---- static device scratch (no runtime allocation) ----
__device__ __align__(16) uint2    g_A_h[SEQ * 256];        // hidden fp16 [4096][1024]
__device__ __align__(16) uint2    g_W_h[QKV_COLS * 256];   // W fp16 [3072][1024]
__device__ __align__(16) uint32_t g_q_hi[SEQ * 512];       // Q hi-plane
__device__ __align__(16) uint32_t g_k_hi[SEQ * 512];       // K hi-plane
__device__ __align__(16) uint32_t g_v_hi[SEQ * 512];       // V hi-plane
__device__ __align__(16) uint32_t g_vT_hi[NH * HD * 2048]; // [h*64+d][kv-pairs]

// ---------------------------------------------------------------------------
// helpers
// ---------------------------------------------------------------------------
__device__ __forceinline__ uint32_t pack2(float x0, float x1) {
    uint32_t hp;
    asm("cvt.rn.f16x2.f32 %0, %1, %2;" : "=r"(hp) : "f"(x1), "f"(x0));
    return hp;
}

__device__ __forceinline__ float ex2(float x) {
    float y;
    asm("ex2.approx.f32 %0, %1;" : "=f"(y) : "f"(x));
    return y;
}

// D(16x8,f32) += A(16x16,f16) * B(16x8,f16)
__device__ __forceinline__ void mma16816(float* d, const uint32_t* a,
                                         uint32_t b0, uint32_t b1) {
    asm volatile(
        "mma.sync.aligned.m16n8k16.row.col.f32.f16.f16.f32 "
        "{%0,%1,%2,%3}, {%4,%5,%6,%7}, {%8,%9}, {%0,%1,%2,%3};"
        : "+f"(d[0]), "+f"(d[1]), "+f"(d[2]), "+f"(d[3])
        : "r"(a[0]), "r"(a[1]), "r"(a[2]), "r"(a[3]), "r"(b0), "r"(b1));
}

// ---------------------------------------------------------------------------
// Prep: fp32 -> dense fp16
// ---------------------------------------------------------------------------
__global__ void pack_kernel(const float4* __restrict__ src,
                            uint2* __restrict__ dst, int n4) {
    int i = blockIdx.x * blockDim.x + threadIdx.x;
    if (i >= n4) return;
    float4 v = src[i];
    dst[i] = make_uint2(pack2(v.x, v.y), pack2(v.z, v.w));
}

// ---------------------------------------------------------------------------
// Kernel 1: QKV GEMM, single-pass fp16 mma.  C[4096,3072] = A @ W^T + bias
//   Epilogue: all regions -> dense fp16 hi-planes (Q scaled by QSCALE).
//   128x128x32 tile, 256 threads; warp grid 4(M)x2(N), warp tile 32x64.
// ---------------------------------------------------------------------------
#define GST 20   // smem row stride in u32 per k-step tile (16 u32 data + pad)

__global__ __launch_bounds__(256)
void qkv_gemm_mma(const float* __restrict__ bias) {
    extern __shared__ uint32_t smg[];
    uint32_t* As = smg;                    // [2][128*GST]
    uint32_t* Bs = smg + 2 * 128 * GST;    // [2][128*GST]
    uint4* As4 = reinterpret_cast<uint4*>(As);
    uint4* Bs4 = reinterpret_cast<uint4*>(Bs);

    const int t = threadIdx.x;
    const int warp = t >> 5, lane = t & 31;
    const int g = lane >> 2, tq = lane & 3;
    const int wm = warp & 3;
    const int wn = warp >> 2;
    const int bm = blockIdx.y * 128;
    const int bn = blockIdx.x * 128;

    const uint4* A4 = reinterpret_cast<const uint4*>(g_A_h);   // row = 128 u4
    const uint4* B4 = reinterpret_cast<const uint4*>(g_W_h);   // row = 128 u4

    const int lr4 = t >> 2;      // loader row 0..63 (+64*i)
    const int lc4 = t & 3;       // loader uint4 col 0..3

    float acc[2][8][4];
    #pragma unroll
    for (int mt = 0; mt < 2; ++mt)
        #pragma unroll
        for (int nt = 0; nt < 8; ++nt)
            #pragma unroll
            for (int j = 0; j < 4; ++j) acc[mt][nt][j] = 0.f;

    uint4 pa[2], pb[2];
    // preload kt = 0
    #pragma unroll
    for (int i = 0; i < 2; ++i) {
        int r = lr4 + i * 64;
        pa[i] = A4[(bm + r) * 128 + lc4];
        pb[i] = B4[(bn + r) * 128 + lc4];
    }
    #pragma unroll
    for (int i = 0; i < 2; ++i) {
        int r = lr4 + i * 64;
        As4[r * 5 + lc4] = pa[i];
        Bs4[r * 5 + lc4] = pb[i];
    }
    __syncthreads();

    for (int kt = 0; kt < 32; ++kt) {
        const int cur = kt & 1;
        if (kt < 31) {
            #pragma unroll
            for (int i = 0; i < 2; ++i) {
                int r = lr4 + i * 64;
                pa[i] = A4[(bm + r) * 128 + (kt + 1) * 4 + lc4];
                pb[i] = B4[(bn + r) * 128 + (kt + 1) * 4 + lc4];
            }
        }
        const uint32_t* Ab = As + cur * (128 * GST);
        const uint32_t* Bb = Bs + cur * (128 * GST);

        #pragma unroll
        for (int ks = 0; ks < 2; ++ks) {
            const int kb = ks * 8;
            uint32_t a[2][4];
            #pragma unroll
            for (int mt = 0; mt < 2; ++mt) {
                int row = wm * 32 + mt * 16 + g;
                a[mt][0] = Ab[row * GST + kb + tq];
                a[mt][1] = Ab[(row + 8) * GST + kb + tq];
                a[mt][2] = Ab[row * GST + kb + tq + 4];
                a[mt][3] = Ab[(row + 8) * GST + kb + tq + 4];
            }
            uint32_t b[8][2];
            #pragma unroll
            for (int nt = 0; nt < 8; ++nt) {
                int col = wn * 64 + nt * 8 + g;
                b[nt][0] = Bb[col * GST + kb + tq];
                b[nt][1] = Bb[col * GST + kb + tq + 4];
            }
            #pragma unroll
            for (int mt = 0; mt < 2; ++mt)
                #pragma unroll
                for (int nt = 0; nt < 8; ++nt)
                    mma16816(acc[mt][nt], a[mt], b[nt][0], b[nt][1]);
        }
        if (kt < 31) {
            uint4* Ad = As4 + (cur ^ 1) * (128 * GST / 4);
            uint4* Bd = Bs4 + (cur ^ 1) * (128 * GST / 4);
            #pragma unroll
            for (int i = 0; i < 2; ++i) {
                int r = lr4 + i * 64;
                Ad[r * 5 + lc4] = pa[i];
                Bd[r * 5 + lc4] = pb[i];
            }
        }
        __syncthreads();
    }

    // epilogue: + bias; all regions -> dense hi-planes
    const int region = bn >> 10;         // 0=Q, 1=K, 2=V
    const float scale = (region == 0) ? QSCALE : 1.0f;
    uint32_t* dst = (region == 0) ? g_q_hi : (region == 1) ? g_k_hi : g_v_hi;
    const int cbase = bn - (region << 10);
    #pragma unroll
    for (int mt = 0; mt < 2; ++mt) {
        int r0 = bm + wm * 32 + mt * 16 + g;
        #pragma unroll
        for (int nt = 0; nt < 8; ++nt) {
            int col0 = cbase + wn * 64 + nt * 8 + 2 * tq;
            float b0 = bias[(region << 10) + col0];
            float b1 = bias[(region << 10) + col0 + 1];
            float v00 = (acc[mt][nt][0] + b0) * scale;
            float v01 = (acc[mt][nt][1] + b1) * scale;
            float v10 = (acc[mt][nt][2] + b0) * scale;
            float v11 = (acc[mt][nt][3] + b1) * scale;
            int c = col0 >> 1;
            dst[r0 * 512 + c]       = pack2(v00, v01);
            dst[(r0 + 8) * 512 + c] = pack2(v10, v11);
        }
    }
}

// ---------------------------------------------------------------------------
// Kernel 2: V transpose  g_v_hi -> g_vT_hi[h][d][kv-pair]
// ---------------------------------------------------------------------------
__global__ void vT_kernel() {
    int i = blockIdx.x * 256 + threadIdx.x;       // 16*64*2048 total
    int m2 = i & 2047;
    int d  = (i >> 11) & 63;
    int h  = i >> 17;
    int col = h * 32 + (d >> 1);
    uint32_t p0 = g_v_hi[(2 * m2) * 512 + col];
    uint32_t p1 = g_v_hi[(2 * m2 + 1) * 512 + col];
    uint32_t sh = (d & 1) * 16;
    g_vT_hi[((h * 64 + d) << 11) + m2] =
        ((p0 >> sh) & 0xffffu) | (((p1 >> sh) & 0xffffu) << 16);
}

// ---------------------------------------------------------------------------
// Kernel 3: flash attention, fp16 mma, hi-planes only (1-pass S, 1-pass PV).
//   Per iter: prefetch LDG(t+1); S(t) mma; PV(t-1) mma; softmax(t); stores.
//   K double-buffered, V triple-buffered. Consistent quantized normalizer.
// ---------------------------------------------------------------------------
#define KST 36          // K/V/Q smem row stride in uint32 (144B)
#define KBUF (64 * KST)
#define SM_K_OFF (128 * KST)             // Q = 128 rows x KST u32 = 4608 u32
#define SM_V_OFF (SM_K_OFF + 2 * KBUF)
#define ATTN_SMEM ((SM_V_OFF + 3 * KBUF) * 4)   // 64512 bytes -> 3 CTAs/SM
#define NT (SEQ / 64)

__global__ __launch_bounds__(256)
void attn_mma(const float* __restrict__ trace, float* __restrict__ out) {
    extern __shared__ uint32_t smw[];
    uint32_t* Qs  = smw;
    uint32_t* Ks  = smw + SM_K_OFF;
    uint32_t* Vs  = smw + SM_V_OFF;
    uint4*    Qs4 = reinterpret_cast<uint4*>(Qs);

    const int t = threadIdx.x;
    const int warp = t >> 5, lane = t & 31;
    const int g = lane >> 2, tq = lane & 3;
    const int h = blockIdx.y;
    const int q0 = blockIdx.x * 128;

    const uint4* QH4 = reinterpret_cast<const uint4*>(g_q_hi);      // row = 128 u4
    const uint4* KH4 = reinterpret_cast<const uint4*>(g_k_hi);      // row = 128 u4
    const uint4* VT4 = reinterpret_cast<const uint4*>(g_vT_hi);     // row = 512 u4

    // ---- load Q tile to smem (hi-plane, 128 rows x 8 uint4) ----
    #pragma unroll
    for (int j = 0; j < 4; ++j) {
        int f = t + 256 * j;
        int r = f >> 3, c = f & 7;
        Qs4[r * (KST / 4) + c] = QH4[(q0 + r) * 128 + h * 8 + c];
    }

    // K/V loader mapping: rows kr, kr+32; uint4 col kc
    const int kr = t >> 3;        // 0..31
    const int kc = t & 7;

    // ---- preload KV tile 0 ----
    uint4 pk[2], pv[2];
    #pragma unroll
    for (int i = 0; i < 2; ++i) {
        int r = kr + i * 32;
        pk[i] = KH4[r * 128 + h * 8 + kc];
        pv[i] = VT4[(h * 64 + r) * 512 + kc];
    }
    #pragma unroll
    for (int i = 0; i < 2; ++i) {
        int r = kr + i * 32;
        *reinterpret_cast<uint4*>(&Ks[r * KST + 4 * kc]) = pk[i];
        *reinterpret_cast<uint4*>(&Vs[r * KST + 4 * kc]) = pv[i];
    }
    __syncthreads();

    // ---- Q fragments -> registers (hi only) ----
    const int qr = warp * 16;
    uint32_t qh[4][4];
    #pragma unroll
    for (int ks = 0; ks < 4; ++ks) {
        qh[ks][0] = Qs[(qr + g) * KST + 8 * ks + tq];
        qh[ks][1] = Qs[(qr + g + 8) * KST + 8 * ks + tq];
        qh[ks][2] = Qs[(qr + g) * KST + 8 * ks + tq + 4];
        qh[ks][3] = Qs[(qr + g + 8) * KST + 8 * ks + tq + 4];
    }

    float m0 = -1e30f, m1 = -1e30f, l0 = 0.f, l1 = 0.f;
    float o[8][4];
    #pragma unroll
    for (int nt = 0; nt < 8; ++nt)
        #pragma unroll
        for (int j = 0; j < 4; ++j) o[nt][j] = 0.f;

    uint32_t ph[4][4];   // quantized P of the PREVIOUS tile

    for (int it = 0; it < NT; ++it) {
        // ---- prefetch next KV tile (gmem -> regs) ----
        if (it < NT - 1) {
            int kv0 = (it + 1) * 64;
            #pragma unroll
            for (int i = 0; i < 2; ++i) {
                int r = kr + i * 32;
                pk[i] = KH4[(kv0 + r) * 128 + h * 8 + kc];
                pv[i] = VT4[(h * 64 + r) * 512 + (it + 1) * 8 + kc];
            }
        }

        // ---- S(t) = Q_hi @ K_hi^T  (single pass) ----
        const uint32_t* Kb = Ks + (it & 1) * KBUF;
        float s[8][4];
        #pragma unroll
        for (int nt = 0; nt < 8; ++nt)
            #pragma unroll
            for (int j = 0; j < 4; ++j) s[nt][j] = 0.f;

        #pragma unroll
        for (int ks = 0; ks < 4; ++ks) {
            #pragma unroll
            for (int nt = 0; nt < 8; ++nt) {
                int n = nt * 8 + g;
                uint32_t e0 = Kb[n * KST + 8 * ks + tq];
                uint32_t e1 = Kb[n * KST + 8 * ks + tq + 4];
                mma16816(s[nt], qh[ks], e0, e1);
            }
        }

        // ---- PV(t-1): O += P_prev @ V_prev  (drains under softmax) ----
        if (it > 0) {
            const uint32_t* Vb = Vs + ((it - 1) % 3) * KBUF;
            #pragma unroll
            for (int ks = 0; ks < 4; ++ks) {
                #pragma unroll
                for (int nt = 0; nt < 8; ++nt) {
                    int n = nt * 8 + g;
                    uint32_t e0 = Vb[n * KST + 8 * ks + tq];
                    uint32_t e1 = Vb[n * KST + 8 * ks + tq + 4];
                    mma16816(o[nt], ph[ks], e0, e1);
                }
            }
        }

        // ---- softmax(t): max, exp2, pack, l  (independent of o) ----
        float rm0 = -1e30f, rm1 = -1e30f;
        #pragma unroll
        for (int nt = 0; nt < 8; ++nt) {
            rm0 = fmaxf(rm0, fmaxf(s[nt][0], s[nt][1]));
            rm1 = fmaxf(rm1, fmaxf(s[nt][2], s[nt][3]));
        }
        #pragma unroll
        for (int w = 1; w < 4; w <<= 1) {
            rm0 = fmaxf(rm0, __shfl_xor_sync(0xffffffffu, rm0, w));
            rm1 = fmaxf(rm1, __shfl_xor_sync(0xffffffffu, rm1, w));
        }
        float n0 = fmaxf(m0, rm0), n1 = fmaxf(m1, rm1);
        float a0 = ex2(m0 - n0), a1 = ex2(m1 - n1);
        m0 = n0; m1 = n1;

        float rs0 = 0.f, rs1 = 0.f;
        #pragma unroll
        for (int ks = 0; ks < 4; ++ks) {
            float p00 = ex2(s[2 * ks][0] - n0);
            float p01 = ex2(s[2 * ks][1] - n0);
            float p02 = ex2(s[2 * ks][2] - n1);
            float p03 = ex2(s[2 * ks][3] - n1);
            float p10 = ex2(s[2 * ks + 1][0] - n0);
            float p11 = ex2(s[2 * ks + 1][1] - n0);
            float p12 = ex2(s[2 * ks + 1][2] - n1);
            float p13 = ex2(s[2 * ks + 1][3] - n1);
            ph[ks][0] = pack2(p00, p01);
            ph[ks][1] = pack2(p02, p03);
            ph[ks][2] = pack2(p10, p11);
            ph[ks][3] = pack2(p12, p13);
            float2 q00 = __half22float2(*reinterpret_cast<__half2*>(&ph[ks][0]));
            float2 q01 = __half22float2(*reinterpret_cast<__half2*>(&ph[ks][1]));
            float2 q10 = __half22float2(*reinterpret_cast<__half2*>(&ph[ks][2]));
            float2 q11 = __half22float2(*reinterpret_cast<__half2*>(&ph[ks][3]));
            rs0 += (q00.x + q00.y) + (q10.x + q10.y);
            rs1 += (q01.x + q01.y) + (q11.x + q11.y);
        }
        #pragma unroll
        for (int w = 1; w < 4; w <<= 1) {
            rs0 += __shfl_xor_sync(0xffffffffu, rs0, w);
            rs1 += __shfl_xor_sync(0xffffffffu, rs1, w);
        }
        l0 = l0 * a0 + rs0;
        l1 = l1 * a1 + rs1;

        // o-scale last (needs PV(t-1) results -> overlap)
        #pragma unroll
        for (int nt = 0; nt < 8; ++nt) {
            o[nt][0] *= a0; o[nt][1] *= a0;
            o[nt][2] *= a1; o[nt][3] *= a1;
        }

        // ---- store prefetched tile (t+1) ----
        if (it < NT - 1) {
            uint32_t* Kd = Ks + ((it + 1) & 1) * KBUF;
            uint32_t* Vd = Vs + ((it + 1) % 3) * KBUF;
            #pragma unroll
            for (int i = 0; i < 2; ++i) {
                int r = kr + i * 32;
                *reinterpret_cast<uint4*>(&Kd[r * KST + 4 * kc]) = pk[i];
                *reinterpret_cast<uint4*>(&Vd[r * KST + 4 * kc]) = pv[i];
            }
        }
        __syncthreads();
    }

    // ---- final PV for the last tile ----
    {
        const uint32_t* Vb = Vs + ((NT - 1) % 3) * KBUF;
        #pragma unroll
        for (int ks = 0; ks < 4; ++ks) {
            #pragma unroll
            for (int nt = 0; nt < 8; ++nt) {
                int n = nt * 8 + g;
                uint32_t e0 = Vb[n * KST + 8 * ks + tq];
                uint32_t e1 = Vb[n * KST + 8 * ks + tq + 4];
                mma16816(o[nt], ph[ks], e0, e1);
            }
        }
    }

    // ---- epilogue: 1/l, Hebbian diag, store ----
    float inv0 = 1.f / l0, inv1 = 1.f / l1;
    int row0 = q0 + qr + g, row1 = row0 + 8;
    #pragma unroll
    for (int nt = 0; nt < 8; ++nt) {
        int d0 = nt * 8 + 2 * tq;
        float dd0 = trace[h * 4096 + d0 * 65];
        float dd1 = trace[h * 4096 + (d0 + 1) * 65];
        float2 r0 = make_float2(o[nt][0] * inv0 * dd0, o[nt][1] * inv0 * dd1);
        float2 r1 = make_float2(o[nt][2] * inv1 * dd0, o[nt][3] * inv1 * dd1);
        *(float2*)&out[row0 * EMB + h * HD + d0] = r0;
        *(float2*)&out[row1 * EMB + h * HD + d0] = r1;
    }
}

// ---------------------------------------------------------------------------
extern "C" void kernel_launch(void* const* d_in, const int* in_sizes, int n_in,
                              void* d_out, int out_size) {
    (void)in_sizes; (void)n_in; (void)out_size;
    const float* hidden = (const float*)d_in[0];   // [1,4096,1024]
    const float* W      = (const float*)d_in[1];   // [3072,1024]
    const float* bias   = (const float*)d_in[2];   // [3072]
    const float* trace  = (const float*)d_in[3];   // [16,64,64]
    float* out = (float*)d_out;                    // [1,4096,1024]

    uint2* dA; cudaGetSymbolAddress((void**)&dA, g_A_h);
    uint2* dW; cudaGetSymbolAddress((void**)&dW, g_W_h);

    // prep: pack inputs to fp16
    {
        int n4a = SEQ * EMB / 4;
        pack_kernel<<<(n4a + 255) / 256, 256>>>((const float4*)hidden, dA, n4a);
        int n4w = QKV_COLS * EMB / 4;
        pack_kernel<<<(n4w + 255) / 256, 256>>>((const float4*)W, dW, n4w);
    }

    static int inited = 0;
    if (!inited) {
        cudaFuncSetAttribute(qkv_gemm_mma,
                             cudaFuncAttributeMaxDynamicSharedMemorySize, 40960);
        cudaFuncSetAttribute(attn_mma,
                             cudaFuncAttributeMaxDynamicSharedMemorySize, ATTN_SMEM);
        inited = 1;
    }

    qkv_gemm_mma<<<dim3(QKV_COLS / 128, SEQ / 128), 256, 40960>>>(bias);
    vT_kernel<<<(NH * HD * 2048) / 256, 256>>>();
    attn_mma<<<dim3(SEQ / 128, NH), 256, ATTN_SMEM>>>(trace, out);
}